// round 10
// baseline (speedup 1.0000x reference)
#include <cuda_runtime.h>
#include <cuda_bf16.h>
#include <cstdint>

// MegaNeRF MoE head via mma.sync (HMMA) bf16 3-split — portable to the
// harness's non-'a' compute_103 target.
//
// Round 9: occupancy fix. 512 threads / 16 warps per CTA (4M x 4N warp grid,
// warp tile 32x64) -> ~120 regs/thread (was 255 with 8 warps), 4 warps/SMSP.
// B staging now uses cp.async.cg (no reg round-trip).

#define NPTS   131072
#define NEXP   8
#define DIN    90
#define HID    256
#define XCOLS  93
#define BM     128
#define NTH    512
#define NKS    6                      // k-steps of 16 (K=96 padded)
#define NTILES 32                     // 256 / 8
#define MTILES 8                      // 128 / 16
#define FRAG_B_U32 (NTILES * NKS * 64)    // 12288 u32 per split
#define FRAG_A_U32 (MTILES * NKS * 128)   // 6144  u32 per split

__device__ uint32_t g_w1frag[NEXP][2][FRAG_B_U32];   // [expert][hi/lo][frag]

// ---- smem byte offsets ----
#define SO_WGT 0                                   // 128*8 f32 = 4096
#define SO_B1  (SO_WGT + 4096)                     // 256 f32
#define SO_W2  (SO_B1 + 1024)                      // 256*4 f32
#define SO_RED (SO_W2 + 4096)                      // 128*4 f32
#define SO_A   (SO_RED + 2048)                     // 2*6144*4  = 49152
#define SO_B   (SO_A + 2 * FRAG_A_U32 * 4)         // 2*12288*4 = 98304
#define SO_X   SO_B                                // x tile aliases B (pre-loop)
#define SMEM_BYTES (SO_B + 2 * FRAG_B_U32 * 4)     // 158720 B

// ---- prep: W1 -> fragment-major bf16 hi/lo (runs once) ----
static __global__ void prep_kernel(const float* __restrict__ W1) {
    int gid = blockIdx.x * blockDim.x + threadIdx.x;
    if (gid >= NEXP * FRAG_B_U32) return;
    int e   = gid / FRAG_B_U32;
    int f   = gid % FRAG_B_U32;
    int nt  = f / (NKS * 64);
    int rem = f % (NKS * 64);
    int ks  = rem >> 6;
    int l2  = rem & 63;
    int lane = l2 >> 1, reg = l2 & 1;
    int n  = nt * 8 + (lane >> 2);
    int k0 = ks * 16 + (lane & 3) * 2 + reg * 8;
    const float* w = W1 + (size_t)e * DIN * HID;
    float v0 = (k0     < DIN) ? __ldg(w + k0 * HID + n)       : 0.0f;
    float v1 = (k0 + 1 < DIN) ? __ldg(w + (k0 + 1) * HID + n) : 0.0f;
    __nv_bfloat16 h0 = __float2bfloat16(v0), h1 = __float2bfloat16(v1);
    __nv_bfloat16 l0 = __float2bfloat16(v0 - __bfloat162float(h0));
    __nv_bfloat16 l1 = __float2bfloat16(v1 - __bfloat162float(h1));
    g_w1frag[e][0][f] = (uint32_t)__bfloat16_as_ushort(h0)
                      | ((uint32_t)__bfloat16_as_ushort(h1) << 16);
    g_w1frag[e][1][f] = (uint32_t)__bfloat16_as_ushort(l0)
                      | ((uint32_t)__bfloat16_as_ushort(l1) << 16);
}

__device__ __forceinline__ void mma16816(float* d, const uint32_t* a,
                                         const uint32_t* b) {
    asm volatile(
        "mma.sync.aligned.m16n8k16.row.col.f32.bf16.bf16.f32 "
        "{%0,%1,%2,%3}, {%4,%5,%6,%7}, {%8,%9}, {%0,%1,%2,%3};"
        : "+f"(d[0]), "+f"(d[1]), "+f"(d[2]), "+f"(d[3])
        : "r"(a[0]), "r"(a[1]), "r"(a[2]), "r"(a[3]), "r"(b[0]), "r"(b[1]));
}

__device__ __forceinline__ void cp_async16(uint32_t dst, const void* src) {
    asm volatile("cp.async.cg.shared.global [%0], [%1], 16;"
                 :: "r"(dst), "l"(src) : "memory");
}

static __global__ void __launch_bounds__(NTH, 1)
meganerf_mma_kernel(const float* __restrict__ x,
                    const float* __restrict__ cent,
                    const float* __restrict__ b1,
                    const float* __restrict__ W2,
                    const float* __restrict__ b2,
                    float* __restrict__ out)
{
    extern __shared__ char smem[];
    float*    wgt_s = (float*)(smem + SO_WGT);
    float*    b1_s  = (float*)(smem + SO_B1);
    float*    w2_s  = (float*)(smem + SO_W2);
    float*    red_s = (float*)(smem + SO_RED);
    uint32_t* As    = (uint32_t*)(smem + SO_A);
    uint32_t* Bs    = (uint32_t*)(smem + SO_B);
    float*    xs    = (float*)(smem + SO_X);     // [128][96], aliases Bs
    const uint32_t bs_u32 = (uint32_t)__cvta_generic_to_shared(Bs);

    const int tid    = threadIdx.x;
    const int lane   = tid & 31;
    const int wid    = tid >> 5;       // 0..15
    const int warp_m = wid & 3;        // rows 32*warp_m .. +32
    const int warp_n = wid >> 2;       // cols 64*warp_n .. +64
    const long n0    = (long)blockIdx.x * BM;

    // ---- stage x tile coalesced into xs [128][96] ----
    const float* xt = x + n0 * XCOLS;
    for (int i = tid; i < BM * XCOLS; i += NTH) {
        int p = i / XCOLS, c = i - p * XCOLS;
        xs[p * 96 + c] = __ldg(xt + i);
    }
    for (int i = tid; i < BM * 4; i += NTH) red_s[i] = 0.0f;
    __syncthreads();

    // ---- gating weights (threads 0..127, one point each) ----
    if (tid < BM) {
        float px = xs[tid * 96 + 0], py = xs[tid * 96 + 1], pz = xs[tid * 96 + 2];
        float d[NEXP], mind = 3.402823466e38f;
        #pragma unroll
        for (int e = 0; e < NEXP; e++) {
            float dx = px - __ldg(&cent[e * 3 + 0]);
            float dy = py - __ldg(&cent[e * 3 + 1]);
            float dz = pz - __ldg(&cent[e * 3 + 2]);
            float dd = sqrtf(dx * dx + dy * dy + dz * dz);
            d[e] = dd; mind = fminf(mind, dd);
        }
        float thr = 2.0f * mind, s = 0.0f, inv[NEXP];
        #pragma unroll
        for (int e = 0; e < NEXP; e++) {
            float iv = (d[e] > thr) ? 0.0f : 1.0f / (d[e] + 1e-8f);
            inv[e] = iv; s += iv;
        }
        float rs = 1.0f / s;
        #pragma unroll
        for (int e = 0; e < NEXP; e++) wgt_s[tid * NEXP + e] = inv[e] * rs;
    }

    // ---- build A fragments (hi/lo) from xs ----
    for (int f = tid; f < FRAG_A_U32; f += NTH) {
        int mt  = f / (NKS * 128);
        int rem = f % (NKS * 128);
        int ks  = rem >> 7;
        int l2  = rem & 127;
        int lf  = l2 >> 2, rg = l2 & 3;
        int row = mt * 16 + (lf >> 2) + (rg & 1) * 8;
        int k0  = ks * 16 + (lf & 3) * 2 + (rg >> 1) * 8;
        float v0 = (k0     < DIN) ? xs[row * 96 + 3 + k0]     : 0.0f;
        float v1 = (k0 + 1 < DIN) ? xs[row * 96 + 3 + k0 + 1] : 0.0f;
        __nv_bfloat16 h0 = __float2bfloat16(v0), h1 = __float2bfloat16(v1);
        __nv_bfloat16 l0 = __float2bfloat16(v0 - __bfloat162float(h0));
        __nv_bfloat16 l1 = __float2bfloat16(v1 - __bfloat162float(h1));
        uint32_t hp = (uint32_t)__bfloat16_as_ushort(h0)
                    | ((uint32_t)__bfloat16_as_ushort(h1) << 16);
        uint32_t lp = (uint32_t)__bfloat16_as_ushort(l0)
                    | ((uint32_t)__bfloat16_as_ushort(l1) << 16);
        // As readers run after the next __syncthreads; the xs alias is first
        // overwritten by expert 0's B copy, which is also after that sync.
        As[f]               = hp;
        As[FRAG_A_U32 + f]  = lp;
    }

    float acc_out[4][4];
    #pragma unroll
    for (int i = 0; i < 4; i++)
        #pragma unroll
        for (int o = 0; o < 4; o++) acc_out[i][o] = 0.0f;

    for (int e = 0; e < NEXP; e++) {
        __syncthreads();   // prior readers of Bs/b1_s/w2_s (and xs) done

        // ---- B fragments (hi+lo, 98 KB) via cp.async ----
        {
            const char* src = (const char*)&g_w1frag[e][0][0];
            for (int i = tid; i < (2 * FRAG_B_U32) / 4; i += NTH)
                cp_async16(bs_u32 + 16u * i, src + 16 * i);
            asm volatile("cp.async.commit_group;" ::: "memory");
        }
        for (int i = tid; i < HID; i += NTH) b1_s[i] = __ldg(&b1[e * HID + i]);
        for (int i = tid; i < HID * 4; i += NTH)
            w2_s[i] = __ldg(&W2[e * HID * 4 + i]);
        asm volatile("cp.async.wait_group 0;" ::: "memory");
        __syncthreads();

        // ---- 3-split mma: acc[2 mt][8 nt][4] fp32 ----
        float acc[2][8][4];
        #pragma unroll
        for (int m = 0; m < 2; m++)
            #pragma unroll
            for (int n = 0; n < 8; n++)
                #pragma unroll
                for (int r = 0; r < 4; r++) acc[m][n][r] = 0.0f;

        #pragma unroll
        for (int t = 0; t < 3; t++) {
            const int sA = (t == 2) ? 1 : 0;
            const int sB = (t == 1) ? 1 : 0;
            const uint32_t* Ab = As + sA * FRAG_A_U32;
            const uint32_t* Bb = Bs + sB * FRAG_B_U32;
            #pragma unroll
            for (int ks = 0; ks < NKS; ks++) {
                uint32_t a[2][4], b[8][2];
                #pragma unroll
                for (int m = 0; m < 2; m++)
                    *(uint4*)a[m] = *(const uint4*)(Ab
                        + ((warp_m * 2 + m) * NKS + ks) * 128 + lane * 4);
                #pragma unroll
                for (int n = 0; n < 8; n++)
                    *(uint2*)b[n] = *(const uint2*)(Bb
                        + ((warp_n * 8 + n) * NKS + ks) * 64 + lane * 2);
                #pragma unroll
                for (int m = 0; m < 2; m++)
                    #pragma unroll
                    for (int n = 0; n < 8; n++)
                        mma16816(acc[m][n], a[m], b[n]);
            }
        }

        // ---- epilogue: bias+relu+gate, contract with W2 into acc_out ----
        #pragma unroll
        for (int m = 0; m < 2; m++) {
            int r0 = warp_m * 32 + m * 16 + (lane >> 2);
            float wp0 = wgt_s[r0 * NEXP + e];
            float wp1 = wgt_s[(r0 + 8) * NEXP + e];
            #pragma unroll
            for (int n = 0; n < 8; n++) {
                int c0 = warp_n * 64 + n * 8 + (lane & 3) * 2;
                float bc0 = b1_s[c0], bc1 = b1_s[c0 + 1];
                float4 w20 = *(const float4*)(w2_s + c0 * 4);
                float4 w21 = *(const float4*)(w2_s + (c0 + 1) * 4);
                float* A = acc[m][n];
                float h00 = fmaxf(A[0] + bc0, 0.0f) * wp0;
                float h01 = fmaxf(A[1] + bc1, 0.0f) * wp0;
                float h10 = fmaxf(A[2] + bc0, 0.0f) * wp1;
                float h11 = fmaxf(A[3] + bc1, 0.0f) * wp1;
                float* o0 = acc_out[m * 2];
                float* o1 = acc_out[m * 2 + 1];
                o0[0] = fmaf(h00, w20.x, fmaf(h01, w21.x, o0[0]));
                o0[1] = fmaf(h00, w20.y, fmaf(h01, w21.y, o0[1]));
                o0[2] = fmaf(h00, w20.z, fmaf(h01, w21.z, o0[2]));
                o0[3] = fmaf(h00, w20.w, fmaf(h01, w21.w, o0[3]));
                o1[0] = fmaf(h10, w20.x, fmaf(h11, w21.x, o1[0]));
                o1[1] = fmaf(h10, w20.y, fmaf(h11, w21.y, o1[1]));
                o1[2] = fmaf(h10, w20.z, fmaf(h11, w21.z, o1[2]));
                o1[3] = fmaf(h10, w20.w, fmaf(h11, w21.w, o1[3]));
            }
        }
    }

    // ---- reduce over the 4 lanes sharing a row, then across warp_n ----
    #pragma unroll
    for (int i = 0; i < 4; i++)
        #pragma unroll
        for (int o = 0; o < 4; o++) {
            float v = acc_out[i][o];
            v += __shfl_xor_sync(0xffffffffu, v, 1);
            v += __shfl_xor_sync(0xffffffffu, v, 2);
            acc_out[i][o] = v;
        }
    if ((lane & 3) == 0) {
        #pragma unroll
        for (int m = 0; m < 2; m++) {
            #pragma unroll
            for (int h = 0; h < 2; h++) {
                int row = warp_m * 32 + m * 16 + (lane >> 2) + h * 8;
                #pragma unroll
                for (int o = 0; o < 4; o++)
                    atomicAdd(&red_s[row * 4 + o], acc_out[m * 2 + h][o]);
            }
        }
    }
    __syncthreads();

    if (tid < BM) {
        float4 v = *(const float4*)(red_s + tid * 4);
        #pragma unroll
        for (int e = 0; e < NEXP; e++) {
            float wpe = wgt_s[tid * NEXP + e];
            v.x = fmaf(wpe, __ldg(&b2[e * 4 + 0]), v.x);
            v.y = fmaf(wpe, __ldg(&b2[e * 4 + 1]), v.y);
            v.z = fmaf(wpe, __ldg(&b2[e * 4 + 2]), v.z);
            v.w = fmaf(wpe, __ldg(&b2[e * 4 + 3]), v.w);
        }
        *(float4*)(out + (n0 + tid) * 4) = v;
    }
}

extern "C" void kernel_launch(void* const* d_in, const int* in_sizes, int n_in,
                              void* d_out, int out_size)
{
    const float* x    = (const float*)d_in[0];
    const float* cent = (const float*)d_in[1];
    const float* W1   = (const float*)d_in[2];
    const float* b1   = (const float*)d_in[3];
    const float* W2   = (const float*)d_in[4];
    const float* b2   = (const float*)d_in[5];
    float* out = (float*)d_out;
    (void)in_sizes; (void)n_in; (void)out_size;

    prep_kernel<<<(NEXP * FRAG_B_U32 + 255) / 256, 256>>>(W1);

    cudaFuncSetAttribute(meganerf_mma_kernel,
                         cudaFuncAttributeMaxDynamicSharedMemorySize, SMEM_BYTES);
    meganerf_mma_kernel<<<NPTS / BM, NTH, SMEM_BYTES>>>(x, cent, b1, W2, b2, out);
}

// round 11
// speedup vs baseline: 1.2348x; 1.2348x over previous
#include <cuda_runtime.h>
#include <cuda_bf16.h>
#include <cstdint>

// MegaNeRF MoE head via mma.sync (HMMA) bf16 3-split.
// Round 10: software-pipelined B staging (double-buffered cp.async at
// half-expert granularity, 16 phases) + split-fused ks loop (each fragment
// read from smem exactly once per ks) + all expert side-tables preloaded.

#define NPTS   131072
#define NEXP   8
#define DIN    90
#define HID    256
#define XCOLS  93
#define BM     128
#define NTH    512
#define NKS    6                          // k-steps of 16 (K=96 padded)
#define NTILES 32                         // 256 / 8
#define MTILES 8                          // 128 / 16
#define FRAG_B_U32 (NTILES * NKS * 64)    // 12288 u32 per split
#define FRAG_A_U32 (MTILES * NKS * 128)   // 6144  u32 per split
#define HALF_B_U32 (FRAG_B_U32 / 2)       // 6144 u32 (16 n-tiles)
#define NPHASE (NEXP * 2)

__device__ uint32_t g_w1frag[NEXP][2][FRAG_B_U32];   // [expert][hi/lo][frag]

// ---- smem byte offsets ----
#define SO_WGT  0                                  // 128*8 f32      = 4096
#define SO_B1A  (SO_WGT + 4096)                    // 8*256 f32      = 8192
#define SO_W2A  (SO_B1A + 8192)                    // 8*1024 f32     = 32768
#define SO_RED  (SO_W2A + 32768)                   // 128*4 f32      = 2048
#define SO_A    (SO_RED + 2048)                    // 2*6144*4       = 49152
#define SO_BUF0 (SO_A + 49152)                     // 12288*4        = 49152
#define SO_BUF1 (SO_BUF0 + 49152)                  // 12288*4        = 49152
#define SO_X    SO_BUF1                            // x tile aliases buf1
#define SMEM_BYTES (SO_BUF1 + 49152)               // 194560 B

// ---- prep: W1 -> fragment-major bf16 hi/lo (runs once) ----
static __global__ void prep_kernel(const float* __restrict__ W1) {
    int gid = blockIdx.x * blockDim.x + threadIdx.x;
    if (gid >= NEXP * FRAG_B_U32) return;
    int e   = gid / FRAG_B_U32;
    int f   = gid % FRAG_B_U32;
    int nt  = f / (NKS * 64);
    int rem = f % (NKS * 64);
    int ks  = rem >> 6;
    int l2  = rem & 63;
    int lane = l2 >> 1, reg = l2 & 1;
    int n  = nt * 8 + (lane >> 2);
    int k0 = ks * 16 + (lane & 3) * 2 + reg * 8;
    const float* w = W1 + (size_t)e * DIN * HID;
    float v0 = (k0     < DIN) ? __ldg(w + k0 * HID + n)       : 0.0f;
    float v1 = (k0 + 1 < DIN) ? __ldg(w + (k0 + 1) * HID + n) : 0.0f;
    __nv_bfloat16 h0 = __float2bfloat16(v0), h1 = __float2bfloat16(v1);
    __nv_bfloat16 l0 = __float2bfloat16(v0 - __bfloat162float(h0));
    __nv_bfloat16 l1 = __float2bfloat16(v1 - __bfloat162float(h1));
    g_w1frag[e][0][f] = (uint32_t)__bfloat16_as_ushort(h0)
                      | ((uint32_t)__bfloat16_as_ushort(h1) << 16);
    g_w1frag[e][1][f] = (uint32_t)__bfloat16_as_ushort(l0)
                      | ((uint32_t)__bfloat16_as_ushort(l1) << 16);
}

__device__ __forceinline__ void mma16816(float* d, const uint32_t* a,
                                         const uint32_t* b) {
    asm volatile(
        "mma.sync.aligned.m16n8k16.row.col.f32.bf16.bf16.f32 "
        "{%0,%1,%2,%3}, {%4,%5,%6,%7}, {%8,%9}, {%0,%1,%2,%3};"
        : "+f"(d[0]), "+f"(d[1]), "+f"(d[2]), "+f"(d[3])
        : "r"(a[0]), "r"(a[1]), "r"(a[2]), "r"(a[3]), "r"(b[0]), "r"(b[1]));
}

__device__ __forceinline__ void cp_async16(uint32_t dst, const void* src) {
    asm volatile("cp.async.cg.shared.global [%0], [%1], 16;"
                 :: "r"(dst), "l"(src) : "memory");
}

// prefetch B (hi+lo) for phase p = (e, h) into smem buffer at dst_u32
__device__ __forceinline__ void issue_b_copy(int p, uint32_t dst_u32, int tid) {
    int e = p >> 1, h = p & 1;
    const char* srch = (const char*)&g_w1frag[e][0][h * HALF_B_U32];
    const char* srcl = (const char*)&g_w1frag[e][1][h * HALF_B_U32];
    #pragma unroll
    for (int i = tid; i < HALF_B_U32 / 4; i += NTH) {          // 1536 chunks
        cp_async16(dst_u32 + 16u * i, srch + 16 * i);
        cp_async16(dst_u32 + 4u * HALF_B_U32 + 16u * i, srcl + 16 * i);
    }
    asm volatile("cp.async.commit_group;" ::: "memory");
}

static __global__ void __launch_bounds__(NTH, 1)
meganerf_mma_kernel(const float* __restrict__ x,
                    const float* __restrict__ cent,
                    const float* __restrict__ b1,
                    const float* __restrict__ W2,
                    const float* __restrict__ b2,
                    float* __restrict__ out)
{
    extern __shared__ char smem[];
    float*    wgt_s  = (float*)(smem + SO_WGT);
    float*    b1_all = (float*)(smem + SO_B1A);   // [8][256]
    float*    w2_all = (float*)(smem + SO_W2A);   // [8][256][4]
    float*    red_s  = (float*)(smem + SO_RED);
    uint32_t* As     = (uint32_t*)(smem + SO_A);
    float*    xs     = (float*)(smem + SO_X);     // [128][96], aliases buf1
    uint32_t* bufp[2] = { (uint32_t*)(smem + SO_BUF0), (uint32_t*)(smem + SO_BUF1) };
    const uint32_t buf_u32[2] = {
        (uint32_t)__cvta_generic_to_shared(smem + SO_BUF0),
        (uint32_t)__cvta_generic_to_shared(smem + SO_BUF1) };

    const int tid    = threadIdx.x;
    const int lane   = tid & 31;
    const int wid    = tid >> 5;       // 0..15
    const int warp_m = wid & 3;        // rows 32*warp_m .. +32
    const int warp_n = wid >> 2;       // 32-col slice within the 128-col half
    const long n0    = (long)blockIdx.x * BM;

    // ---- phase-0 B prefetch first: overlaps all setup below ----
    issue_b_copy(0, buf_u32[0], tid);

    // ---- stage x tile coalesced into xs [128][96] ----
    const float* xt = x + n0 * XCOLS;
    for (int i = tid; i < BM * XCOLS; i += NTH) {
        int p = i / XCOLS, c = i - p * XCOLS;
        xs[p * 96 + c] = __ldg(xt + i);
    }
    for (int i = tid; i < BM * 4; i += NTH) red_s[i] = 0.0f;
    // side tables for all experts
    for (int i = tid; i < NEXP * HID; i += NTH) b1_all[i] = __ldg(b1 + i);
    for (int i = tid; i < NEXP * HID * 4; i += NTH) w2_all[i] = __ldg(W2 + i);
    __syncthreads();

    // ---- gating weights (threads 0..127, one point each) ----
    if (tid < BM) {
        float px = xs[tid * 96 + 0], py = xs[tid * 96 + 1], pz = xs[tid * 96 + 2];
        float d[NEXP], mind = 3.402823466e38f;
        #pragma unroll
        for (int e = 0; e < NEXP; e++) {
            float dx = px - __ldg(&cent[e * 3 + 0]);
            float dy = py - __ldg(&cent[e * 3 + 1]);
            float dz = pz - __ldg(&cent[e * 3 + 2]);
            float dd = sqrtf(dx * dx + dy * dy + dz * dz);
            d[e] = dd; mind = fminf(mind, dd);
        }
        float thr = 2.0f * mind, s = 0.0f, inv[NEXP];
        #pragma unroll
        for (int e = 0; e < NEXP; e++) {
            float iv = (d[e] > thr) ? 0.0f : 1.0f / (d[e] + 1e-8f);
            inv[e] = iv; s += iv;
        }
        float rs = 1.0f / s;
        #pragma unroll
        for (int e = 0; e < NEXP; e++) wgt_s[tid * NEXP + e] = inv[e] * rs;
    }

    // ---- build A fragments (hi/lo) from xs ----
    for (int f = tid; f < FRAG_A_U32; f += NTH) {
        int mt  = f / (NKS * 128);
        int rem = f % (NKS * 128);
        int ks  = rem >> 7;
        int l2  = rem & 127;
        int lf  = l2 >> 2, rg = l2 & 3;
        int row = mt * 16 + (lf >> 2) + (rg & 1) * 8;
        int k0  = ks * 16 + (lf & 3) * 2 + (rg >> 1) * 8;
        float v0 = (k0     < DIN) ? xs[row * 96 + 3 + k0]     : 0.0f;
        float v1 = (k0 + 1 < DIN) ? xs[row * 96 + 3 + k0 + 1] : 0.0f;
        __nv_bfloat16 h0 = __float2bfloat16(v0), h1 = __float2bfloat16(v1);
        __nv_bfloat16 l0 = __float2bfloat16(v0 - __bfloat162float(h0));
        __nv_bfloat16 l1 = __float2bfloat16(v1 - __bfloat162float(h1));
        As[f]              = (uint32_t)__bfloat16_as_ushort(h0)
                           | ((uint32_t)__bfloat16_as_ushort(h1) << 16);
        As[FRAG_A_U32 + f] = (uint32_t)__bfloat16_as_ushort(l0)
                           | ((uint32_t)__bfloat16_as_ushort(l1) << 16);
    }

    float acc_out[4][4];
    #pragma unroll
    for (int i = 0; i < 4; i++)
        #pragma unroll
        for (int o = 0; o < 4; o++) acc_out[i][o] = 0.0f;

    for (int p = 0; p < NPHASE; p++) {
        const int e = p >> 1, h = p & 1, par = p & 1;
        // all warps done with the buffer phase p+1 will overwrite
        __syncthreads();
        if (p + 1 < NPHASE)
            issue_b_copy(p + 1, buf_u32[(p + 1) & 1], tid);
        if (p + 1 < NPHASE)
            asm volatile("cp.async.wait_group 1;" ::: "memory");
        else
            asm volatile("cp.async.wait_group 0;" ::: "memory");
        __syncthreads();   // buffer par is ready for all warps

        const uint32_t* Bh = bufp[par];                 // hi split, 16 n-tiles
        const uint32_t* Bl = bufp[par] + HALF_B_U32;    // lo split

        // ---- split-fused mma: warp tile 32 rows x 32 cols, acc[2][4][4] ----
        float acc[2][4][4];
        #pragma unroll
        for (int m = 0; m < 2; m++)
            #pragma unroll
            for (int n = 0; n < 4; n++)
                #pragma unroll
                for (int r = 0; r < 4; r++) acc[m][n][r] = 0.0f;

        #pragma unroll
        for (int ks = 0; ks < NKS; ks++) {
            uint32_t ah[2][4], al[2][4], bh[4][2], bl[4][2];
            #pragma unroll
            for (int m = 0; m < 2; m++) {
                int mt = warp_m * 2 + m;
                *(uint4*)ah[m] = *(const uint4*)(As
                    + (mt * NKS + ks) * 128 + lane * 4);
                *(uint4*)al[m] = *(const uint4*)(As + FRAG_A_U32
                    + (mt * NKS + ks) * 128 + lane * 4);
            }
            #pragma unroll
            for (int n = 0; n < 4; n++) {
                int ntl = warp_n * 4 + n;
                *(uint2*)bh[n] = *(const uint2*)(Bh
                    + (ntl * NKS + ks) * 64 + lane * 2);
                *(uint2*)bl[n] = *(const uint2*)(Bl
                    + (ntl * NKS + ks) * 64 + lane * 2);
            }
            #pragma unroll
            for (int m = 0; m < 2; m++)
                #pragma unroll
                for (int n = 0; n < 4; n++)
                    mma16816(acc[m][n], ah[m], bh[n]);
            #pragma unroll
            for (int m = 0; m < 2; m++)
                #pragma unroll
                for (int n = 0; n < 4; n++)
                    mma16816(acc[m][n], ah[m], bl[n]);
            #pragma unroll
            for (int m = 0; m < 2; m++)
                #pragma unroll
                for (int n = 0; n < 4; n++)
                    mma16816(acc[m][n], al[m], bh[n]);
        }

        // ---- epilogue: bias+relu+gate, contract with W2 into acc_out ----
        const float* b1e = b1_all + e * HID;
        const float* w2e = w2_all + e * HID * 4;
        #pragma unroll
        for (int m = 0; m < 2; m++) {
            int r0 = warp_m * 32 + m * 16 + (lane >> 2);
            float wp0 = wgt_s[r0 * NEXP + e];
            float wp1 = wgt_s[(r0 + 8) * NEXP + e];
            #pragma unroll
            for (int n = 0; n < 4; n++) {
                int c0 = h * 128 + (warp_n * 4 + n) * 8 + (lane & 3) * 2;
                float bc0 = b1e[c0], bc1 = b1e[c0 + 1];
                float4 w20 = *(const float4*)(w2e + c0 * 4);
                float4 w21 = *(const float4*)(w2e + (c0 + 1) * 4);
                float* A = acc[m][n];
                float h00 = fmaxf(A[0] + bc0, 0.0f) * wp0;
                float h01 = fmaxf(A[1] + bc1, 0.0f) * wp0;
                float h10 = fmaxf(A[2] + bc0, 0.0f) * wp1;
                float h11 = fmaxf(A[3] + bc1, 0.0f) * wp1;
                float* o0 = acc_out[m * 2];
                float* o1 = acc_out[m * 2 + 1];
                o0[0] = fmaf(h00, w20.x, fmaf(h01, w21.x, o0[0]));
                o0[1] = fmaf(h00, w20.y, fmaf(h01, w21.y, o0[1]));
                o0[2] = fmaf(h00, w20.z, fmaf(h01, w21.z, o0[2]));
                o0[3] = fmaf(h00, w20.w, fmaf(h01, w21.w, o0[3]));
                o1[0] = fmaf(h10, w20.x, fmaf(h11, w21.x, o1[0]));
                o1[1] = fmaf(h10, w20.y, fmaf(h11, w21.y, o1[1]));
                o1[2] = fmaf(h10, w20.z, fmaf(h11, w21.z, o1[2]));
                o1[3] = fmaf(h10, w20.w, fmaf(h11, w21.w, o1[3]));
            }
        }
    }

    // ---- reduce over the 4 lanes sharing a row, then across warps ----
    #pragma unroll
    for (int i = 0; i < 4; i++)
        #pragma unroll
        for (int o = 0; o < 4; o++) {
            float v = acc_out[i][o];
            v += __shfl_xor_sync(0xffffffffu, v, 1);
            v += __shfl_xor_sync(0xffffffffu, v, 2);
            acc_out[i][o] = v;
        }
    if ((lane & 3) == 0) {
        #pragma unroll
        for (int m = 0; m < 2; m++) {
            #pragma unroll
            for (int rh = 0; rh < 2; rh++) {
                int row = warp_m * 32 + m * 16 + (lane >> 2) + rh * 8;
                #pragma unroll
                for (int o = 0; o < 4; o++)
                    atomicAdd(&red_s[row * 4 + o], acc_out[m * 2 + rh][o]);
            }
        }
    }
    __syncthreads();

    if (tid < BM) {
        float4 v = *(const float4*)(red_s + tid * 4);
        #pragma unroll
        for (int e = 0; e < NEXP; e++) {
            float wpe = wgt_s[tid * NEXP + e];
            v.x = fmaf(wpe, __ldg(&b2[e * 4 + 0]), v.x);
            v.y = fmaf(wpe, __ldg(&b2[e * 4 + 1]), v.y);
            v.z = fmaf(wpe, __ldg(&b2[e * 4 + 2]), v.z);
            v.w = fmaf(wpe, __ldg(&b2[e * 4 + 3]), v.w);
        }
        *(float4*)(out + (n0 + tid) * 4) = v;
    }
}

extern "C" void kernel_launch(void* const* d_in, const int* in_sizes, int n_in,
                              void* d_out, int out_size)
{
    const float* x    = (const float*)d_in[0];
    const float* cent = (const float*)d_in[1];
    const float* W1   = (const float*)d_in[2];
    const float* b1   = (const float*)d_in[3];
    const float* W2   = (const float*)d_in[4];
    const float* b2   = (const float*)d_in[5];
    float* out = (float*)d_out;
    (void)in_sizes; (void)n_in; (void)out_size;

    prep_kernel<<<(NEXP * FRAG_B_U32 + 255) / 256, 256>>>(W1);

    cudaFuncSetAttribute(meganerf_mma_kernel,
                         cudaFuncAttributeMaxDynamicSharedMemorySize, SMEM_BYTES);
    meganerf_mma_kernel<<<NPTS / BM, NTH, SMEM_BYTES>>>(x, cent, b1, W2, b2, out);
}

// round 14
// speedup vs baseline: 1.4136x; 1.1448x over previous
#include <cuda_runtime.h>
#include <cuda_bf16.h>
#include <cstdint>

// MegaNeRF MoE head via mma.sync (HMMA) bf16 3-split.
// Round 11: 2 CTAs/SM for bubble overlap. 256-thread CTAs
// (__launch_bounds__(256,2) -> 128 regs), smem trimmed to ~102 KB:
// quarter-expert double-buffered cp.async phases (32 phases, 24.6 KB each),
// b1/W2 epilogue reads via L2-hot __ldg broadcasts instead of smem tables.
// Cross-CTA interleaving hides per-phase barriers/waits/epilogues that held
// tensor util at 50% with a single resident CTA.

#define NPTS   131072
#define NEXP   8
#define DIN    90
#define HID    256
#define XCOLS  93
#define BM     128
#define NTH    256
#define NKS    6                          // k-steps of 16 (K=96 padded)
#define NTILES 32                         // 256 / 8
#define MTILES 8                          // 128 / 16
#define FRAG_B_U32 (NTILES * NKS * 64)    // 12288 u32 per split
#define FRAG_A_U32 (MTILES * NKS * 128)   // 6144  u32 per split
#define QB_U32     (FRAG_B_U32 / 4)       // 3072 u32 (8 n-tiles)
#define NPHASE     (NEXP * 4)             // 32 quarter-expert phases

__device__ uint32_t g_w1frag[NEXP][2][FRAG_B_U32];   // [expert][hi/lo][frag]

// ---- smem byte offsets ----
#define SO_WGT  0                                  // 128*8 f32  = 4096
#define SO_RED  4096                               // 128*4 f32  = 2048
#define SO_A    6144                               // 2*6144*4   = 49152
#define SO_BUF0 (SO_A + 49152)                     // 24576
#define SO_BUF1 (SO_BUF0 + 24576)                  // 24576
#define SO_X    SO_BUF0                            // x tile aliases both bufs
#define SMEM_BYTES (SO_BUF1 + 24576)               // 104448 B  (2 CTAs/SM ok)

// ---- prep: W1 -> fragment-major bf16 hi/lo (runs once) ----
static __global__ void prep_kernel(const float* __restrict__ W1) {
    int gid = blockIdx.x * blockDim.x + threadIdx.x;
    if (gid >= NEXP * FRAG_B_U32) return;
    int e   = gid / FRAG_B_U32;
    int f   = gid % FRAG_B_U32;
    int nt  = f / (NKS * 64);
    int rem = f % (NKS * 64);
    int ks  = rem >> 6;
    int l2  = rem & 63;
    int lane = l2 >> 1, reg = l2 & 1;
    int n  = nt * 8 + (lane >> 2);
    int k0 = ks * 16 + (lane & 3) * 2 + reg * 8;
    const float* w = W1 + (size_t)e * DIN * HID;
    float v0 = (k0     < DIN) ? __ldg(w + k0 * HID + n)       : 0.0f;
    float v1 = (k0 + 1 < DIN) ? __ldg(w + (k0 + 1) * HID + n) : 0.0f;
    __nv_bfloat16 h0 = __float2bfloat16(v0), h1 = __float2bfloat16(v1);
    __nv_bfloat16 l0 = __float2bfloat16(v0 - __bfloat162float(h0));
    __nv_bfloat16 l1 = __float2bfloat16(v1 - __bfloat162float(h1));
    g_w1frag[e][0][f] = (uint32_t)__bfloat16_as_ushort(h0)
                      | ((uint32_t)__bfloat16_as_ushort(h1) << 16);
    g_w1frag[e][1][f] = (uint32_t)__bfloat16_as_ushort(l0)
                      | ((uint32_t)__bfloat16_as_ushort(l1) << 16);
}

__device__ __forceinline__ void mma16816(float* d, const uint32_t* a,
                                         const uint32_t* b) {
    asm volatile(
        "mma.sync.aligned.m16n8k16.row.col.f32.bf16.bf16.f32 "
        "{%0,%1,%2,%3}, {%4,%5,%6,%7}, {%8,%9}, {%0,%1,%2,%3};"
        : "+f"(d[0]), "+f"(d[1]), "+f"(d[2]), "+f"(d[3])
        : "r"(a[0]), "r"(a[1]), "r"(a[2]), "r"(a[3]), "r"(b[0]), "r"(b[1]));
}

__device__ __forceinline__ void cp_async16(uint32_t dst, const void* src) {
    asm volatile("cp.async.cg.shared.global [%0], [%1], 16;"
                 :: "r"(dst), "l"(src) : "memory");
}

// prefetch B (hi+lo) for phase p = (e, q) into smem buffer at dst_u32
__device__ __forceinline__ void issue_b_copy(int p, uint32_t dst_u32, int tid) {
    int e = p >> 2, q = p & 3;
    const char* srch = (const char*)&g_w1frag[e][0][q * QB_U32];
    const char* srcl = (const char*)&g_w1frag[e][1][q * QB_U32];
    #pragma unroll
    for (int i = tid; i < QB_U32 / 4; i += NTH) {              // 768 chunks
        cp_async16(dst_u32 + 16u * i, srch + 16 * i);
        cp_async16(dst_u32 + 4u * QB_U32 + 16u * i, srcl + 16 * i);
    }
    asm volatile("cp.async.commit_group;" ::: "memory");
}

static __global__ void __launch_bounds__(NTH, 2)
meganerf_mma_kernel(const float* __restrict__ x,
                    const float* __restrict__ cent,
                    const float* __restrict__ b1,
                    const float* __restrict__ W2,
                    const float* __restrict__ b2,
                    float* __restrict__ out)
{
    extern __shared__ char smem[];
    float*    wgt_s = (float*)(smem + SO_WGT);
    float*    red_s = (float*)(smem + SO_RED);
    uint32_t* As    = (uint32_t*)(smem + SO_A);
    float*    xs    = (float*)(smem + SO_X);     // [128][96], aliases buffers
    uint32_t* bufp[2] = { (uint32_t*)(smem + SO_BUF0), (uint32_t*)(smem + SO_BUF1) };
    const uint32_t buf_u32[2] = {
        (uint32_t)__cvta_generic_to_shared(smem + SO_BUF0),
        (uint32_t)__cvta_generic_to_shared(smem + SO_BUF1) };

    const int tid    = threadIdx.x;
    const int lane   = tid & 31;
    const int wid    = tid >> 5;       // 0..7
    const int warp_m = wid & 3;        // rows 32*warp_m .. +32
    const int warp_n = wid >> 2;       // 32-col slice within the 64-col quarter
    const long n0    = (long)blockIdx.x * BM;

    // ---- stage x tile coalesced into xs [128][96] ----
    const float* xt = x + n0 * XCOLS;
    for (int i = tid; i < BM * XCOLS; i += NTH) {
        int p = i / XCOLS, c = i - p * XCOLS;
        xs[p * 96 + c] = __ldg(xt + i);
    }
    for (int i = tid; i < BM * 4; i += NTH) red_s[i] = 0.0f;
    __syncthreads();

    // ---- gating weights (threads 0..127, one point each) ----
    if (tid < BM) {
        float px = xs[tid * 96 + 0], py = xs[tid * 96 + 1], pz = xs[tid * 96 + 2];
        float d[NEXP], mind = 3.402823466e38f;
        #pragma unroll
        for (int e = 0; e < NEXP; e++) {
            float dx = px - __ldg(&cent[e * 3 + 0]);
            float dy = py - __ldg(&cent[e * 3 + 1]);
            float dz = pz - __ldg(&cent[e * 3 + 2]);
            float dd = sqrtf(dx * dx + dy * dy + dz * dz);
            d[e] = dd; mind = fminf(mind, dd);
        }
        float thr = 2.0f * mind, s = 0.0f, inv[NEXP];
        #pragma unroll
        for (int e = 0; e < NEXP; e++) {
            float iv = (d[e] > thr) ? 0.0f : 1.0f / (d[e] + 1e-8f);
            inv[e] = iv; s += iv;
        }
        float rs = 1.0f / s;
        #pragma unroll
        for (int e = 0; e < NEXP; e++) wgt_s[tid * NEXP + e] = inv[e] * rs;
    }

    // ---- build A fragments (hi/lo) from xs ----
    for (int f = tid; f < FRAG_A_U32; f += NTH) {
        int mt  = f / (NKS * 128);
        int rem = f % (NKS * 128);
        int ks  = rem >> 7;
        int l2  = rem & 127;
        int lf  = l2 >> 2, rg = l2 & 3;
        int row = mt * 16 + (lf >> 2) + (rg & 1) * 8;
        int k0  = ks * 16 + (lf & 3) * 2 + (rg >> 1) * 8;
        float v0 = (k0     < DIN) ? xs[row * 96 + 3 + k0]     : 0.0f;
        float v1 = (k0 + 1 < DIN) ? xs[row * 96 + 3 + k0 + 1] : 0.0f;
        __nv_bfloat16 h0 = __float2bfloat16(v0), h1 = __float2bfloat16(v1);
        __nv_bfloat16 l0 = __float2bfloat16(v0 - __bfloat162float(h0));
        __nv_bfloat16 l1 = __float2bfloat16(v1 - __bfloat162float(h1));
        As[f]              = (uint32_t)__bfloat16_as_ushort(h0)
                           | ((uint32_t)__bfloat16_as_ushort(h1) << 16);
        As[FRAG_A_U32 + f] = (uint32_t)__bfloat16_as_ushort(l0)
                           | ((uint32_t)__bfloat16_as_ushort(l1) << 16);
    }
    __syncthreads();   // xs fully consumed -> buffers may be overwritten

    issue_b_copy(0, buf_u32[0], tid);   // phase-0 prefetch

    float acc_out[4][4];
    #pragma unroll
    for (int i = 0; i < 4; i++)
        #pragma unroll
        for (int o = 0; o < 4; o++) acc_out[i][o] = 0.0f;

    for (int p = 0; p < NPHASE; p++) {
        const int e = p >> 2, q = p & 3, par = p & 1;
        __syncthreads();   // all warps done with the buffer copy p+1 overwrites
        if (p + 1 < NPHASE) {
            issue_b_copy(p + 1, buf_u32[(p + 1) & 1], tid);
            asm volatile("cp.async.wait_group 1;" ::: "memory");
        } else {
            asm volatile("cp.async.wait_group 0;" ::: "memory");
        }
        __syncthreads();   // buffer par is ready for all warps

        const uint32_t* Bh = bufp[par];            // hi split, 8 n-tiles
        const uint32_t* Bl = bufp[par] + QB_U32;   // lo split

        // ---- split-fused mma: warp tile 32 rows x 32 cols, acc[2][4][4] ----
        float acc[2][4][4];
        #pragma unroll
        for (int m = 0; m < 2; m++)
            #pragma unroll
            for (int n = 0; n < 4; n++)
                #pragma unroll
                for (int r = 0; r < 4; r++) acc[m][n][r] = 0.0f;

        #pragma unroll
        for (int ks = 0; ks < NKS; ks++) {
            uint32_t ah[2][4], al[2][4], bh[4][2], bl[4][2];
            #pragma unroll
            for (int m = 0; m < 2; m++) {
                int mt = warp_m * 2 + m;
                *(uint4*)ah[m] = *(const uint4*)(As
                    + (mt * NKS + ks) * 128 + lane * 4);
                *(uint4*)al[m] = *(const uint4*)(As + FRAG_A_U32
                    + (mt * NKS + ks) * 128 + lane * 4);
            }
            #pragma unroll
            for (int n = 0; n < 4; n++) {
                int ln = warp_n * 4 + n;
                *(uint2*)bh[n] = *(const uint2*)(Bh
                    + (ln * NKS + ks) * 64 + lane * 2);
                *(uint2*)bl[n] = *(const uint2*)(Bl
                    + (ln * NKS + ks) * 64 + lane * 2);
            }
            #pragma unroll
            for (int m = 0; m < 2; m++)
                #pragma unroll
                for (int n = 0; n < 4; n++)
                    mma16816(acc[m][n], ah[m], bh[n]);
            #pragma unroll
            for (int m = 0; m < 2; m++)
                #pragma unroll
                for (int n = 0; n < 4; n++)
                    mma16816(acc[m][n], ah[m], bl[n]);
            #pragma unroll
            for (int m = 0; m < 2; m++)
                #pragma unroll
                for (int n = 0; n < 4; n++)
                    mma16816(acc[m][n], al[m], bh[n]);
        }

        // ---- epilogue: bias+relu+gate, contract with W2 (L2-hot __ldg) ----
        float wp[2][2];
        #pragma unroll
        for (int m = 0; m < 2; m++) {
            int r0 = warp_m * 32 + m * 16 + (lane >> 2);
            wp[m][0] = wgt_s[r0 * NEXP + e];
            wp[m][1] = wgt_s[(r0 + 8) * NEXP + e];
        }
        #pragma unroll
        for (int n = 0; n < 4; n++) {
            int c0 = q * 64 + (warp_n * 4 + n) * 8 + (lane & 3) * 2;
            float2 b1v = __ldg((const float2*)(b1 + e * HID + c0));
            float4 w20 = __ldg((const float4*)(W2 + ((size_t)e * HID + c0) * 4));
            float4 w21 = __ldg((const float4*)(W2 + ((size_t)e * HID + c0 + 1) * 4));
            #pragma unroll
            for (int m = 0; m < 2; m++) {
                float* A = acc[m][n];
                float h00 = fmaxf(A[0] + b1v.x, 0.0f) * wp[m][0];
                float h01 = fmaxf(A[1] + b1v.y, 0.0f) * wp[m][0];
                float h10 = fmaxf(A[2] + b1v.x, 0.0f) * wp[m][1];
                float h11 = fmaxf(A[3] + b1v.y, 0.0f) * wp[m][1];
                float* o0 = acc_out[m * 2];
                float* o1 = acc_out[m * 2 + 1];
                o0[0] = fmaf(h00, w20.x, fmaf(h01, w21.x, o0[0]));
                o0[1] = fmaf(h00, w20.y, fmaf(h01, w21.y, o0[1]));
                o0[2] = fmaf(h00, w20.z, fmaf(h01, w21.z, o0[2]));
                o0[3] = fmaf(h00, w20.w, fmaf(h01, w21.w, o0[3]));
                o1[0] = fmaf(h10, w20.x, fmaf(h11, w21.x, o1[0]));
                o1[1] = fmaf(h10, w20.y, fmaf(h11, w21.y, o1[1]));
                o1[2] = fmaf(h10, w20.z, fmaf(h11, w21.z, o1[2]));
                o1[3] = fmaf(h10, w20.w, fmaf(h11, w21.w, o1[3]));
            }
        }
    }

    // ---- reduce over the 4 lanes sharing a row, then across warps ----
    #pragma unroll
    for (int i = 0; i < 4; i++)
        #pragma unroll
        for (int o = 0; o < 4; o++) {
            float v = acc_out[i][o];
            v += __shfl_xor_sync(0xffffffffu, v, 1);
            v += __shfl_xor_sync(0xffffffffu, v, 2);
            acc_out[i][o] = v;
        }
    if ((lane & 3) == 0) {
        #pragma unroll
        for (int m = 0; m < 2; m++) {
            #pragma unroll
            for (int rh = 0; rh < 2; rh++) {
                int row = warp_m * 32 + m * 16 + (lane >> 2) + rh * 8;
                #pragma unroll
                for (int o = 0; o < 4; o++)
                    atomicAdd(&red_s[row * 4 + o], acc_out[m * 2 + rh][o]);
            }
        }
    }
    __syncthreads();

    if (tid < BM) {
        float4 v = *(const float4*)(red_s + tid * 4);
        #pragma unroll
        for (int e = 0; e < NEXP; e++) {
            float wpe = wgt_s[tid * NEXP + e];
            v.x = fmaf(wpe, __ldg(&b2[e * 4 + 0]), v.x);
            v.y = fmaf(wpe, __ldg(&b2[e * 4 + 1]), v.y);
            v.z = fmaf(wpe, __ldg(&b2[e * 4 + 2]), v.z);
            v.w = fmaf(wpe, __ldg(&b2[e * 4 + 3]), v.w);
        }
        *(float4*)(out + (n0 + tid) * 4) = v;
    }
}

extern "C" void kernel_launch(void* const* d_in, const int* in_sizes, int n_in,
                              void* d_out, int out_size)
{
    const float* x    = (const float*)d_in[0];
    const float* cent = (const float*)d_in[1];
    const float* W1   = (const float*)d_in[2];
    const float* b1   = (const float*)d_in[3];
    const float* W2   = (const float*)d_in[4];
    const float* b2   = (const float*)d_in[5];
    float* out = (float*)d_out;
    (void)in_sizes; (void)n_in; (void)out_size;

    prep_kernel<<<(NEXP * FRAG_B_U32 + 255) / 256, 256>>>(W1);

    cudaFuncSetAttribute(meganerf_mma_kernel,
                         cudaFuncAttributeMaxDynamicSharedMemorySize, SMEM_BYTES);
    meganerf_mma_kernel<<<NPTS / BM, NTH, SMEM_BYTES>>>(x, cent, b1, W2, b2, out);
}

// round 15
// speedup vs baseline: 1.6843x; 1.1915x over previous
#include <cuda_runtime.h>
#include <cuda_bf16.h>
#include <cstdint>

// MegaNeRF MoE head via mma.sync (HMMA) bf16 3-split + GATE-SPARSE expert
// skipping.
// Round 14: dense 3-split is at its tensor floor (255 us @ rt=8); cut the
// work instead. A pre-pass bins points by their 8-bit active-expert mask
// (dist <= 2*min_dist) and permutes them so each CTA's 128 points share
// (mostly) one mask -> CTA runs only its union's experts (~2.5-4 of 8).
// Bitwise-identical output: skipped experts contributed exactly 0.

#define NPTS   131072
#define NEXP   8
#define DIN    90
#define HID    256
#define XCOLS  93
#define BM     128
#define NTH    256
#define NKS    6                          // k-steps of 16 (K=96 padded)
#define NTILES 32
#define MTILES 8
#define FRAG_B_U32 (NTILES * NKS * 64)    // 12288 u32 per split
#define FRAG_A_U32 (MTILES * NKS * 128)   // 6144  u32 per split
#define QB_U32     (FRAG_B_U32 / 4)       // 3072 u32 (8 n-tiles)

__device__ uint32_t g_w1frag[NEXP][2][FRAG_B_U32];
__device__ int           g_perm[NPTS];
__device__ unsigned      g_hist[256];
__device__ unsigned      g_cursor[256];
__device__ unsigned char g_mask[NPTS];

// ---- smem byte offsets ----
#define SO_WGT  0                                  // 128*8 f32 = 4096
#define SO_RED  4096                               // 2048
#define SO_PIDX 6144                               // 128 int = 512
#define SO_LIST 6656                               // mask, cnt, list[8] = 64
#define SO_A    6720                               // 2*6144*4 = 49152
#define SO_BUF0 (SO_A + 49152)                     // 24576
#define SO_BUF1 (SO_BUF0 + 24576)                  // 24576
#define SO_X    SO_BUF0                            // x tile aliases both bufs
#define SMEM_BYTES (SO_BUF1 + 24576)               // 105024 B (2 CTAs/SM)

// ---- prep: W1 -> fragment-major bf16 hi/lo (runs once per launch) ----
static __global__ void prep_kernel(const float* __restrict__ W1) {
    int gid = blockIdx.x * blockDim.x + threadIdx.x;
    if (gid >= NEXP * FRAG_B_U32) return;
    int e   = gid / FRAG_B_U32;
    int f   = gid % FRAG_B_U32;
    int nt  = f / (NKS * 64);
    int rem = f % (NKS * 64);
    int ks  = rem >> 6;
    int l2  = rem & 63;
    int lane = l2 >> 1, reg = l2 & 1;
    int n  = nt * 8 + (lane >> 2);
    int k0 = ks * 16 + (lane & 3) * 2 + reg * 8;
    const float* w = W1 + (size_t)e * DIN * HID;
    float v0 = (k0     < DIN) ? __ldg(w + k0 * HID + n)       : 0.0f;
    float v1 = (k0 + 1 < DIN) ? __ldg(w + (k0 + 1) * HID + n) : 0.0f;
    __nv_bfloat16 h0 = __float2bfloat16(v0), h1 = __float2bfloat16(v1);
    __nv_bfloat16 l0 = __float2bfloat16(v0 - __bfloat162float(h0));
    __nv_bfloat16 l1 = __float2bfloat16(v1 - __bfloat162float(h1));
    g_w1frag[e][0][f] = (uint32_t)__bfloat16_as_ushort(h0)
                      | ((uint32_t)__bfloat16_as_ushort(h1) << 16);
    g_w1frag[e][1][f] = (uint32_t)__bfloat16_as_ushort(l0)
                      | ((uint32_t)__bfloat16_as_ushort(l1) << 16);
}

// ---- binning pre-pass ----
static __global__ void hist_zero_kernel() { g_hist[threadIdx.x] = 0u; }

static __global__ void mask_hist_kernel(const float* __restrict__ x,
                                        const float* __restrict__ cent) {
    int i = blockIdx.x * blockDim.x + threadIdx.x;
    const float* xr = x + (size_t)i * XCOLS;
    float px = __ldg(xr + 0), py = __ldg(xr + 1), pz = __ldg(xr + 2);
    float d[NEXP], mind = 3.402823466e38f;
    #pragma unroll
    for (int e = 0; e < NEXP; e++) {
        float dx = px - __ldg(&cent[e * 3 + 0]);
        float dy = py - __ldg(&cent[e * 3 + 1]);
        float dz = pz - __ldg(&cent[e * 3 + 2]);
        float dd = sqrtf(dx * dx + dy * dy + dz * dz);
        d[e] = dd; mind = fminf(mind, dd);
    }
    float thr = 2.0f * mind;
    unsigned m = 0;
    #pragma unroll
    for (int e = 0; e < NEXP; e++)
        if (!(d[e] > thr)) m |= 1u << e;
    g_mask[i] = (unsigned char)m;
    atomicAdd(&g_hist[m], 1u);
}

static __global__ void scan_kernel() {
    __shared__ unsigned s[256];
    int t = threadIdx.x;
    unsigned own = g_hist[t];
    s[t] = own;
    __syncthreads();
    for (int off = 1; off < 256; off <<= 1) {
        unsigned v = (t >= off) ? s[t - off] : 0u;
        __syncthreads();
        s[t] += v;
        __syncthreads();
    }
    g_cursor[t] = s[t] - own;   // exclusive prefix
}

static __global__ void scatter_kernel() {
    int i = blockIdx.x * blockDim.x + threadIdx.x;
    unsigned m = g_mask[i];
    unsigned pos = atomicAdd(&g_cursor[m], 1u);
    g_perm[pos] = i;
}

__device__ __forceinline__ void mma16816(float* d, const uint32_t* a,
                                         const uint32_t* b) {
    asm volatile(
        "mma.sync.aligned.m16n8k16.row.col.f32.bf16.bf16.f32 "
        "{%0,%1,%2,%3}, {%4,%5,%6,%7}, {%8,%9}, {%0,%1,%2,%3};"
        : "+f"(d[0]), "+f"(d[1]), "+f"(d[2]), "+f"(d[3])
        : "r"(a[0]), "r"(a[1]), "r"(a[2]), "r"(a[3]), "r"(b[0]), "r"(b[1]));
}

__device__ __forceinline__ void cp_async16(uint32_t dst, const void* src) {
    asm volatile("cp.async.cg.shared.global [%0], [%1], 16;"
                 :: "r"(dst), "l"(src) : "memory");
}

// prefetch B (hi+lo) for (expert e, quarter q) into smem at dst_u32
__device__ __forceinline__ void issue_b_copy(int e, int q, uint32_t dst_u32,
                                             int tid) {
    const char* srch = (const char*)&g_w1frag[e][0][q * QB_U32];
    const char* srcl = (const char*)&g_w1frag[e][1][q * QB_U32];
    #pragma unroll
    for (int i = tid; i < QB_U32 / 4; i += NTH) {
        cp_async16(dst_u32 + 16u * i, srch + 16 * i);
        cp_async16(dst_u32 + 4u * QB_U32 + 16u * i, srcl + 16 * i);
    }
    asm volatile("cp.async.commit_group;" ::: "memory");
}

static __global__ void __launch_bounds__(NTH, 2)
meganerf_mma_kernel(const float* __restrict__ x,
                    const float* __restrict__ cent,
                    const float* __restrict__ b1,
                    const float* __restrict__ W2,
                    const float* __restrict__ b2,
                    float* __restrict__ out)
{
    extern __shared__ char smem[];
    float*    wgt_s  = (float*)(smem + SO_WGT);
    float*    red_s  = (float*)(smem + SO_RED);
    int*      pidx_s = (int*)(smem + SO_PIDX);
    unsigned* ls     = (unsigned*)(smem + SO_LIST);  // [0]=mask [1]=cnt [2..9]=list
    uint32_t* As     = (uint32_t*)(smem + SO_A);
    float*    xs     = (float*)(smem + SO_X);        // [128][96], aliases buffers
    uint32_t* bufp[2] = { (uint32_t*)(smem + SO_BUF0), (uint32_t*)(smem + SO_BUF1) };
    const uint32_t buf_u32[2] = {
        (uint32_t)__cvta_generic_to_shared(smem + SO_BUF0),
        (uint32_t)__cvta_generic_to_shared(smem + SO_BUF1) };

    const int tid    = threadIdx.x;
    const int lane   = tid & 31;
    const int wid    = tid >> 5;
    const int warp_m = wid & 3;
    const int warp_n = wid >> 2;
    const long n0    = (long)blockIdx.x * BM;

    if (tid < BM) pidx_s[tid] = g_perm[n0 + tid];
    if (tid == 0) ls[0] = 0u;
    __syncthreads();

    // ---- gather permuted x rows into xs [128][96] ----
    for (int i = tid; i < BM * XCOLS; i += NTH) {
        int p = i / XCOLS, c = i - p * XCOLS;
        xs[p * 96 + c] = __ldg(x + (size_t)pidx_s[p] * XCOLS + c);
    }
    for (int i = tid; i < BM * 4; i += NTH) red_s[i] = 0.0f;
    __syncthreads();

    // ---- gating weights + per-CTA active mask ----
    if (tid < BM) {
        float px = xs[tid * 96 + 0], py = xs[tid * 96 + 1], pz = xs[tid * 96 + 2];
        float d[NEXP], mind = 3.402823466e38f;
        #pragma unroll
        for (int e = 0; e < NEXP; e++) {
            float dx = px - __ldg(&cent[e * 3 + 0]);
            float dy = py - __ldg(&cent[e * 3 + 1]);
            float dz = pz - __ldg(&cent[e * 3 + 2]);
            float dd = sqrtf(dx * dx + dy * dy + dz * dz);
            d[e] = dd; mind = fminf(mind, dd);
        }
        float thr = 2.0f * mind, s = 0.0f, inv[NEXP];
        unsigned m = 0;
        #pragma unroll
        for (int e = 0; e < NEXP; e++) {
            float iv = (d[e] > thr) ? 0.0f : 1.0f / (d[e] + 1e-8f);
            if (iv > 0.0f) m |= 1u << e;
            inv[e] = iv; s += iv;
        }
        float rs = 1.0f / s;
        #pragma unroll
        for (int e = 0; e < NEXP; e++) wgt_s[tid * NEXP + e] = inv[e] * rs;
        atomicOr(&ls[0], m);
    }

    // ---- build A fragments (hi/lo) from xs ----
    for (int f = tid; f < FRAG_A_U32; f += NTH) {
        int mt  = f / (NKS * 128);
        int rem = f % (NKS * 128);
        int ks  = rem >> 7;
        int l2  = rem & 127;
        int lf  = l2 >> 2, rg = l2 & 3;
        int row = mt * 16 + (lf >> 2) + (rg & 1) * 8;
        int k0  = ks * 16 + (lf & 3) * 2 + (rg >> 1) * 8;
        float v0 = (k0     < DIN) ? xs[row * 96 + 3 + k0]     : 0.0f;
        float v1 = (k0 + 1 < DIN) ? xs[row * 96 + 3 + k0 + 1] : 0.0f;
        __nv_bfloat16 h0 = __float2bfloat16(v0), h1 = __float2bfloat16(v1);
        __nv_bfloat16 l0 = __float2bfloat16(v0 - __bfloat162float(h0));
        __nv_bfloat16 l1 = __float2bfloat16(v1 - __bfloat162float(h1));
        As[f]              = (uint32_t)__bfloat16_as_ushort(h0)
                           | ((uint32_t)__bfloat16_as_ushort(h1) << 16);
        As[FRAG_A_U32 + f] = (uint32_t)__bfloat16_as_ushort(l0)
                           | ((uint32_t)__bfloat16_as_ushort(l1) << 16);
    }
    __syncthreads();   // xs consumed; active mask complete

    if (tid == 0) {    // ascending-e active list (deterministic order)
        unsigned m = ls[0], c = 0;
        #pragma unroll
        for (int e = 0; e < NEXP; e++)
            if (m & (1u << e)) ls[2 + c++] = (unsigned)e;
        ls[1] = c;
    }
    __syncthreads();

    const int nact = (int)ls[1];
    const int nph  = nact * 4;

    issue_b_copy((int)ls[2], 0, buf_u32[0], tid);   // phase-0 prefetch

    float acc_out[4][4];
    #pragma unroll
    for (int i = 0; i < 4; i++)
        #pragma unroll
        for (int o = 0; o < 4; o++) acc_out[i][o] = 0.0f;

    for (int p = 0; p < nph; p++) {
        const int e = (int)ls[2 + (p >> 2)], q = p & 3, par = p & 1;
        __syncthreads();   // all warps done with the buffer copy p+1 overwrites
        if (p + 1 < nph) {
            issue_b_copy((int)ls[2 + ((p + 1) >> 2)], (p + 1) & 3,
                         buf_u32[(p + 1) & 1], tid);
            asm volatile("cp.async.wait_group 1;" ::: "memory");
        } else {
            asm volatile("cp.async.wait_group 0;" ::: "memory");
        }
        __syncthreads();   // buffer par ready for all warps

        const uint32_t* Bh = bufp[par];
        const uint32_t* Bl = bufp[par] + QB_U32;

        float acc[2][4][4];
        #pragma unroll
        for (int m = 0; m < 2; m++)
            #pragma unroll
            for (int n = 0; n < 4; n++)
                #pragma unroll
                for (int r = 0; r < 4; r++) acc[m][n][r] = 0.0f;

        #pragma unroll
        for (int ks = 0; ks < NKS; ks++) {
            uint32_t ah[2][4], al[2][4], bh[4][2], bl[4][2];
            #pragma unroll
            for (int m = 0; m < 2; m++) {
                int mt = warp_m * 2 + m;
                *(uint4*)ah[m] = *(const uint4*)(As
                    + (mt * NKS + ks) * 128 + lane * 4);
                *(uint4*)al[m] = *(const uint4*)(As + FRAG_A_U32
                    + (mt * NKS + ks) * 128 + lane * 4);
            }
            #pragma unroll
            for (int n = 0; n < 4; n++) {
                int ln = warp_n * 4 + n;
                *(uint2*)bh[n] = *(const uint2*)(Bh
                    + (ln * NKS + ks) * 64 + lane * 2);
                *(uint2*)bl[n] = *(const uint2*)(Bl
                    + (ln * NKS + ks) * 64 + lane * 2);
            }
            #pragma unroll
            for (int m = 0; m < 2; m++)
                #pragma unroll
                for (int n = 0; n < 4; n++)
                    mma16816(acc[m][n], ah[m], bh[n]);
            #pragma unroll
            for (int m = 0; m < 2; m++)
                #pragma unroll
                for (int n = 0; n < 4; n++)
                    mma16816(acc[m][n], ah[m], bl[n]);
            #pragma unroll
            for (int m = 0; m < 2; m++)
                #pragma unroll
                for (int n = 0; n < 4; n++)
                    mma16816(acc[m][n], al[m], bh[n]);
        }

        // ---- epilogue: bias+relu+gate, contract with W2 (L2-hot __ldg) ----
        float wp[2][2];
        #pragma unroll
        for (int m = 0; m < 2; m++) {
            int r0 = warp_m * 32 + m * 16 + (lane >> 2);
            wp[m][0] = wgt_s[r0 * NEXP + e];
            wp[m][1] = wgt_s[(r0 + 8) * NEXP + e];
        }
        #pragma unroll
        for (int n = 0; n < 4; n++) {
            int c0 = q * 64 + (warp_n * 4 + n) * 8 + (lane & 3) * 2;
            float2 b1v = __ldg((const float2*)(b1 + e * HID + c0));
            float4 w20 = __ldg((const float4*)(W2 + ((size_t)e * HID + c0) * 4));
            float4 w21 = __ldg((const float4*)(W2 + ((size_t)e * HID + c0 + 1) * 4));
            #pragma unroll
            for (int m = 0; m < 2; m++) {
                float* A = acc[m][n];
                float h00 = fmaxf(A[0] + b1v.x, 0.0f) * wp[m][0];
                float h01 = fmaxf(A[1] + b1v.y, 0.0f) * wp[m][0];
                float h10 = fmaxf(A[2] + b1v.x, 0.0f) * wp[m][1];
                float h11 = fmaxf(A[3] + b1v.y, 0.0f) * wp[m][1];
                float* o0 = acc_out[m * 2];
                float* o1 = acc_out[m * 2 + 1];
                o0[0] = fmaf(h00, w20.x, fmaf(h01, w21.x, o0[0]));
                o0[1] = fmaf(h00, w20.y, fmaf(h01, w21.y, o0[1]));
                o0[2] = fmaf(h00, w20.z, fmaf(h01, w21.z, o0[2]));
                o0[3] = fmaf(h00, w20.w, fmaf(h01, w21.w, o0[3]));
                o1[0] = fmaf(h10, w20.x, fmaf(h11, w21.x, o1[0]));
                o1[1] = fmaf(h10, w20.y, fmaf(h11, w21.y, o1[1]));
                o1[2] = fmaf(h10, w20.z, fmaf(h11, w21.z, o1[2]));
                o1[3] = fmaf(h10, w20.w, fmaf(h11, w21.w, o1[3]));
            }
        }
    }

    // ---- reduce over the 4 lanes sharing a row, then across warps ----
    #pragma unroll
    for (int i = 0; i < 4; i++)
        #pragma unroll
        for (int o = 0; o < 4; o++) {
            float v = acc_out[i][o];
            v += __shfl_xor_sync(0xffffffffu, v, 1);
            v += __shfl_xor_sync(0xffffffffu, v, 2);
            acc_out[i][o] = v;
        }
    if ((lane & 3) == 0) {
        #pragma unroll
        for (int m = 0; m < 2; m++) {
            #pragma unroll
            for (int rh = 0; rh < 2; rh++) {
                int row = warp_m * 32 + m * 16 + (lane >> 2) + rh * 8;
                #pragma unroll
                for (int o = 0; o < 4; o++)
                    atomicAdd(&red_s[row * 4 + o], acc_out[m * 2 + rh][o]);
            }
        }
    }
    __syncthreads();

    if (tid < BM) {
        float4 v = *(const float4*)(red_s + tid * 4);
        #pragma unroll
        for (int e = 0; e < NEXP; e++) {
            float wpe = wgt_s[tid * NEXP + e];
            v.x = fmaf(wpe, __ldg(&b2[e * 4 + 0]), v.x);
            v.y = fmaf(wpe, __ldg(&b2[e * 4 + 1]), v.y);
            v.z = fmaf(wpe, __ldg(&b2[e * 4 + 2]), v.z);
            v.w = fmaf(wpe, __ldg(&b2[e * 4 + 3]), v.w);
        }
        *(float4*)(out + (size_t)pidx_s[tid] * 4) = v;
    }
}

extern "C" void kernel_launch(void* const* d_in, const int* in_sizes, int n_in,
                              void* d_out, int out_size)
{
    const float* x    = (const float*)d_in[0];
    const float* cent = (const float*)d_in[1];
    const float* W1   = (const float*)d_in[2];
    const float* b1   = (const float*)d_in[3];
    const float* W2   = (const float*)d_in[4];
    const float* b2   = (const float*)d_in[5];
    float* out = (float*)d_out;
    (void)in_sizes; (void)n_in; (void)out_size;

    prep_kernel<<<(NEXP * FRAG_B_U32 + 255) / 256, 256>>>(W1);
    hist_zero_kernel<<<1, 256>>>();
    mask_hist_kernel<<<NPTS / 256, 256>>>(x, cent);
    scan_kernel<<<1, 256>>>();
    scatter_kernel<<<NPTS / 256, 256>>>();

    cudaFuncSetAttribute(meganerf_mma_kernel,
                         cudaFuncAttributeMaxDynamicSharedMemorySize, SMEM_BYTES);
    meganerf_mma_kernel<<<NPTS / BM, NTH, SMEM_BYTES>>>(x, cent, b1, W2, b2, out);
}

// round 16
// speedup vs baseline: 1.7366x; 1.0311x over previous
#include <cuda_runtime.h>
#include <cuda_bf16.h>
#include <cstdint>

// MegaNeRF MoE head via mma.sync (HMMA) bf16 3-split + gate-sparse expert
// skipping (mean ~6.4/8 active).
// Round 15: phase-tail fix. Each phase's epilogue params (b1/W2 quarter,
// 1.25 KB) are cp.async-staged in the SAME commit group as the B fragments,
// so the epilogue reads smem (29cyc broadcast) instead of chained L2 __ldg
// (~300cyc) right before the phase barrier. Gate weights hoisted above the
// mma loop.

#define NPTS   131072
#define NEXP   8
#define DIN    90
#define HID    256
#define XCOLS  93
#define BM     128
#define NTH    256
#define NKS    6                          // k-steps of 16 (K=96 padded)
#define NTILES 32
#define MTILES 8
#define FRAG_B_U32 (NTILES * NKS * 64)    // 12288 u32 per split
#define FRAG_A_U32 (MTILES * NKS * 128)   // 6144  u32 per split
#define QB_U32     (FRAG_B_U32 / 4)       // 3072 u32 (8 n-tiles)
#define BUF_BYTES  (2 * QB_U32 * 4 + 1280)   // B hi+lo + b1q(256B) + W2q(1024B)
#define OFF_B1Q    (2 * QB_U32 * 4)          // 24576
#define OFF_W2Q    (OFF_B1Q + 256)           // 24832

__device__ uint32_t g_w1frag[NEXP][2][FRAG_B_U32];
__device__ int           g_perm[NPTS];
__device__ unsigned      g_hist[256];
__device__ unsigned      g_cursor[256];
__device__ unsigned char g_mask[NPTS];

// ---- smem byte offsets ----
#define SO_WGT  0                                  // 128*8 f32 = 4096
#define SO_RED  4096                               // 2048
#define SO_PIDX 6144                               // 512
#define SO_LIST 6656                               // 64
#define SO_A    6720                               // 49152
#define SO_BUF0 (SO_A + 49152)                     // 25856
#define SO_BUF1 (SO_BUF0 + BUF_BYTES)
#define SO_X    SO_BUF0                            // x tile aliases both bufs
#define SMEM_BYTES (SO_BUF1 + BUF_BYTES)           // 107584 B (2 CTAs/SM)

// ---- prep: W1 -> fragment-major bf16 hi/lo (runs once per launch) ----
static __global__ void prep_kernel(const float* __restrict__ W1) {
    int gid = blockIdx.x * blockDim.x + threadIdx.x;
    if (gid >= NEXP * FRAG_B_U32) return;
    int e   = gid / FRAG_B_U32;
    int f   = gid % FRAG_B_U32;
    int nt  = f / (NKS * 64);
    int rem = f % (NKS * 64);
    int ks  = rem >> 6;
    int l2  = rem & 63;
    int lane = l2 >> 1, reg = l2 & 1;
    int n  = nt * 8 + (lane >> 2);
    int k0 = ks * 16 + (lane & 3) * 2 + reg * 8;
    const float* w = W1 + (size_t)e * DIN * HID;
    float v0 = (k0     < DIN) ? __ldg(w + k0 * HID + n)       : 0.0f;
    float v1 = (k0 + 1 < DIN) ? __ldg(w + (k0 + 1) * HID + n) : 0.0f;
    __nv_bfloat16 h0 = __float2bfloat16(v0), h1 = __float2bfloat16(v1);
    __nv_bfloat16 l0 = __float2bfloat16(v0 - __bfloat162float(h0));
    __nv_bfloat16 l1 = __float2bfloat16(v1 - __bfloat162float(h1));
    g_w1frag[e][0][f] = (uint32_t)__bfloat16_as_ushort(h0)
                      | ((uint32_t)__bfloat16_as_ushort(h1) << 16);
    g_w1frag[e][1][f] = (uint32_t)__bfloat16_as_ushort(l0)
                      | ((uint32_t)__bfloat16_as_ushort(l1) << 16);
}

// ---- binning pre-pass ----
static __global__ void hist_zero_kernel() { g_hist[threadIdx.x] = 0u; }

static __global__ void mask_hist_kernel(const float* __restrict__ x,
                                        const float* __restrict__ cent) {
    int i = blockIdx.x * blockDim.x + threadIdx.x;
    const float* xr = x + (size_t)i * XCOLS;
    float px = __ldg(xr + 0), py = __ldg(xr + 1), pz = __ldg(xr + 2);
    float d[NEXP], mind = 3.402823466e38f;
    #pragma unroll
    for (int e = 0; e < NEXP; e++) {
        float dx = px - __ldg(&cent[e * 3 + 0]);
        float dy = py - __ldg(&cent[e * 3 + 1]);
        float dz = pz - __ldg(&cent[e * 3 + 2]);
        float dd = sqrtf(dx * dx + dy * dy + dz * dz);
        d[e] = dd; mind = fminf(mind, dd);
    }
    float thr = 2.0f * mind;
    unsigned m = 0;
    #pragma unroll
    for (int e = 0; e < NEXP; e++)
        if (!(d[e] > thr)) m |= 1u << e;
    g_mask[i] = (unsigned char)m;
    atomicAdd(&g_hist[m], 1u);
}

static __global__ void scan_kernel() {
    __shared__ unsigned s[256];
    int t = threadIdx.x;
    unsigned own = g_hist[t];
    s[t] = own;
    __syncthreads();
    for (int off = 1; off < 256; off <<= 1) {
        unsigned v = (t >= off) ? s[t - off] : 0u;
        __syncthreads();
        s[t] += v;
        __syncthreads();
    }
    g_cursor[t] = s[t] - own;   // exclusive prefix
}

static __global__ void scatter_kernel() {
    int i = blockIdx.x * blockDim.x + threadIdx.x;
    unsigned m = g_mask[i];
    unsigned pos = atomicAdd(&g_cursor[m], 1u);
    g_perm[pos] = i;
}

__device__ __forceinline__ void mma16816(float* d, const uint32_t* a,
                                         const uint32_t* b) {
    asm volatile(
        "mma.sync.aligned.m16n8k16.row.col.f32.bf16.bf16.f32 "
        "{%0,%1,%2,%3}, {%4,%5,%6,%7}, {%8,%9}, {%0,%1,%2,%3};"
        : "+f"(d[0]), "+f"(d[1]), "+f"(d[2]), "+f"(d[3])
        : "r"(a[0]), "r"(a[1]), "r"(a[2]), "r"(a[3]), "r"(b[0]), "r"(b[1]));
}

__device__ __forceinline__ void cp_async16(uint32_t dst, const void* src) {
    asm volatile("cp.async.cg.shared.global [%0], [%1], 16;"
                 :: "r"(dst), "l"(src) : "memory");
}

// prefetch B (hi+lo) + epilogue params for (expert e, quarter q)
__device__ __forceinline__ void issue_b_copy(int e, int q, uint32_t dst_u32,
                                             int tid,
                                             const float* __restrict__ b1,
                                             const float* __restrict__ W2) {
    const char* srch = (const char*)&g_w1frag[e][0][q * QB_U32];
    const char* srcl = (const char*)&g_w1frag[e][1][q * QB_U32];
    #pragma unroll
    for (int i = tid; i < QB_U32 / 4; i += NTH) {
        cp_async16(dst_u32 + 16u * i, srch + 16 * i);
        cp_async16(dst_u32 + 4u * QB_U32 + 16u * i, srcl + 16 * i);
    }
    // epilogue params: b1 quarter (16 chunks) + W2 quarter (64 chunks)
    if (tid < 16)
        cp_async16(dst_u32 + OFF_B1Q + 16u * tid,
                   (const char*)(b1 + e * HID + q * 64) + 16 * tid);
    else if (tid < 80)
        cp_async16(dst_u32 + OFF_W2Q + 16u * (tid - 16),
                   (const char*)(W2 + ((size_t)e * HID + q * 64) * 4)
                       + 16 * (tid - 16));
    asm volatile("cp.async.commit_group;" ::: "memory");
}

static __global__ void __launch_bounds__(NTH, 2)
meganerf_mma_kernel(const float* __restrict__ x,
                    const float* __restrict__ cent,
                    const float* __restrict__ b1,
                    const float* __restrict__ W2,
                    const float* __restrict__ b2,
                    float* __restrict__ out)
{
    extern __shared__ char smem[];
    float*    wgt_s  = (float*)(smem + SO_WGT);
    float*    red_s  = (float*)(smem + SO_RED);
    int*      pidx_s = (int*)(smem + SO_PIDX);
    unsigned* ls     = (unsigned*)(smem + SO_LIST);
    uint32_t* As     = (uint32_t*)(smem + SO_A);
    float*    xs     = (float*)(smem + SO_X);
    char*     bufc[2] = { smem + SO_BUF0, smem + SO_BUF1 };
    const uint32_t buf_u32[2] = {
        (uint32_t)__cvta_generic_to_shared(smem + SO_BUF0),
        (uint32_t)__cvta_generic_to_shared(smem + SO_BUF1) };

    const int tid    = threadIdx.x;
    const int lane   = tid & 31;
    const int wid    = tid >> 5;
    const int warp_m = wid & 3;
    const int warp_n = wid >> 2;
    const long n0    = (long)blockIdx.x * BM;

    if (tid < BM) pidx_s[tid] = g_perm[n0 + tid];
    if (tid == 0) ls[0] = 0u;
    __syncthreads();

    // ---- gather permuted x rows into xs [128][96] ----
    for (int i = tid; i < BM * XCOLS; i += NTH) {
        int p = i / XCOLS, c = i - p * XCOLS;
        xs[p * 96 + c] = __ldg(x + (size_t)pidx_s[p] * XCOLS + c);
    }
    for (int i = tid; i < BM * 4; i += NTH) red_s[i] = 0.0f;
    __syncthreads();

    // ---- gating weights + per-CTA active mask ----
    if (tid < BM) {
        float px = xs[tid * 96 + 0], py = xs[tid * 96 + 1], pz = xs[tid * 96 + 2];
        float d[NEXP], mind = 3.402823466e38f;
        #pragma unroll
        for (int e = 0; e < NEXP; e++) {
            float dx = px - __ldg(&cent[e * 3 + 0]);
            float dy = py - __ldg(&cent[e * 3 + 1]);
            float dz = pz - __ldg(&cent[e * 3 + 2]);
            float dd = sqrtf(dx * dx + dy * dy + dz * dz);
            d[e] = dd; mind = fminf(mind, dd);
        }
        float thr = 2.0f * mind, s = 0.0f, inv[NEXP];
        unsigned m = 0;
        #pragma unroll
        for (int e = 0; e < NEXP; e++) {
            float iv = (d[e] > thr) ? 0.0f : 1.0f / (d[e] + 1e-8f);
            if (iv > 0.0f) m |= 1u << e;
            inv[e] = iv; s += iv;
        }
        float rs = 1.0f / s;
        #pragma unroll
        for (int e = 0; e < NEXP; e++) wgt_s[tid * NEXP + e] = inv[e] * rs;
        atomicOr(&ls[0], m);
    }

    // ---- build A fragments (hi/lo) from xs ----
    for (int f = tid; f < FRAG_A_U32; f += NTH) {
        int mt  = f / (NKS * 128);
        int rem = f % (NKS * 128);
        int ks  = rem >> 7;
        int l2  = rem & 127;
        int lf  = l2 >> 2, rg = l2 & 3;
        int row = mt * 16 + (lf >> 2) + (rg & 1) * 8;
        int k0  = ks * 16 + (lf & 3) * 2 + (rg >> 1) * 8;
        float v0 = (k0     < DIN) ? xs[row * 96 + 3 + k0]     : 0.0f;
        float v1 = (k0 + 1 < DIN) ? xs[row * 96 + 3 + k0 + 1] : 0.0f;
        __nv_bfloat16 h0 = __float2bfloat16(v0), h1 = __float2bfloat16(v1);
        __nv_bfloat16 l0 = __float2bfloat16(v0 - __bfloat162float(h0));
        __nv_bfloat16 l1 = __float2bfloat16(v1 - __bfloat162float(h1));
        As[f]              = (uint32_t)__bfloat16_as_ushort(h0)
                           | ((uint32_t)__bfloat16_as_ushort(h1) << 16);
        As[FRAG_A_U32 + f] = (uint32_t)__bfloat16_as_ushort(l0)
                           | ((uint32_t)__bfloat16_as_ushort(l1) << 16);
    }
    __syncthreads();   // xs consumed; active mask complete

    if (tid == 0) {
        unsigned m = ls[0], c = 0;
        #pragma unroll
        for (int e = 0; e < NEXP; e++)
            if (m & (1u << e)) ls[2 + c++] = (unsigned)e;
        ls[1] = c;
    }
    __syncthreads();

    const int nact = (int)ls[1];
    const int nph  = nact * 4;

    issue_b_copy((int)ls[2], 0, buf_u32[0], tid, b1, W2);

    float acc_out[4][4];
    #pragma unroll
    for (int i = 0; i < 4; i++)
        #pragma unroll
        for (int o = 0; o < 4; o++) acc_out[i][o] = 0.0f;

    for (int p = 0; p < nph; p++) {
        const int e = (int)ls[2 + (p >> 2)], par = p & 1;
        __syncthreads();   // all warps done with the buffer copy p+1 overwrites
        if (p + 1 < nph) {
            issue_b_copy((int)ls[2 + ((p + 1) >> 2)], (p + 1) & 3,
                         buf_u32[(p + 1) & 1], tid, b1, W2);
            asm volatile("cp.async.wait_group 1;" ::: "memory");
        } else {
            asm volatile("cp.async.wait_group 0;" ::: "memory");
        }
        __syncthreads();   // buffer par ready for all warps

        const uint32_t* Bh   = (const uint32_t*)bufc[par];
        const uint32_t* Bl   = Bh + QB_U32;
        const float*    b1q  = (const float*)(bufc[par] + OFF_B1Q);
        const float*    w2q  = (const float*)(bufc[par] + OFF_W2Q);

        // hoist gate weights (cheap LDS, consumed in epilogue)
        float wp[2][2];
        #pragma unroll
        for (int m = 0; m < 2; m++) {
            int r0 = warp_m * 32 + m * 16 + (lane >> 2);
            wp[m][0] = wgt_s[r0 * NEXP + e];
            wp[m][1] = wgt_s[(r0 + 8) * NEXP + e];
        }

        float acc[2][4][4];
        #pragma unroll
        for (int m = 0; m < 2; m++)
            #pragma unroll
            for (int n = 0; n < 4; n++)
                #pragma unroll
                for (int r = 0; r < 4; r++) acc[m][n][r] = 0.0f;

        #pragma unroll
        for (int ks = 0; ks < NKS; ks++) {
            uint32_t ah[2][4], al[2][4], bh[4][2], bl[4][2];
            #pragma unroll
            for (int m = 0; m < 2; m++) {
                int mt = warp_m * 2 + m;
                *(uint4*)ah[m] = *(const uint4*)(As
                    + (mt * NKS + ks) * 128 + lane * 4);
                *(uint4*)al[m] = *(const uint4*)(As + FRAG_A_U32
                    + (mt * NKS + ks) * 128 + lane * 4);
            }
            #pragma unroll
            for (int n = 0; n < 4; n++) {
                int ln = warp_n * 4 + n;
                *(uint2*)bh[n] = *(const uint2*)(Bh
                    + (ln * NKS + ks) * 64 + lane * 2);
                *(uint2*)bl[n] = *(const uint2*)(Bl
                    + (ln * NKS + ks) * 64 + lane * 2);
            }
            #pragma unroll
            for (int m = 0; m < 2; m++)
                #pragma unroll
                for (int n = 0; n < 4; n++)
                    mma16816(acc[m][n], ah[m], bh[n]);
            #pragma unroll
            for (int m = 0; m < 2; m++)
                #pragma unroll
                for (int n = 0; n < 4; n++)
                    mma16816(acc[m][n], ah[m], bl[n]);
            #pragma unroll
            for (int m = 0; m < 2; m++)
                #pragma unroll
                for (int n = 0; n < 4; n++)
                    mma16816(acc[m][n], al[m], bh[n]);
        }

        // ---- epilogue: bias+relu+gate, contract with W2 (staged smem) ----
        #pragma unroll
        for (int n = 0; n < 4; n++) {
            int c = (warp_n * 4 + n) * 8 + (lane & 3) * 2;   // 0..63 in quarter
            float2 b1v = *(const float2*)(b1q + c);
            float4 w20 = *(const float4*)(w2q + c * 4);
            float4 w21 = *(const float4*)(w2q + (c + 1) * 4);
            #pragma unroll
            for (int m = 0; m < 2; m++) {
                float* A = acc[m][n];
                float h00 = fmaxf(A[0] + b1v.x, 0.0f) * wp[m][0];
                float h01 = fmaxf(A[1] + b1v.y, 0.0f) * wp[m][0];
                float h10 = fmaxf(A[2] + b1v.x, 0.0f) * wp[m][1];
                float h11 = fmaxf(A[3] + b1v.y, 0.0f) * wp[m][1];
                float* o0 = acc_out[m * 2];
                float* o1 = acc_out[m * 2 + 1];
                o0[0] = fmaf(h00, w20.x, fmaf(h01, w21.x, o0[0]));
                o0[1] = fmaf(h00, w20.y, fmaf(h01, w21.y, o0[1]));
                o0[2] = fmaf(h00, w20.z, fmaf(h01, w21.z, o0[2]));
                o0[3] = fmaf(h00, w20.w, fmaf(h01, w21.w, o0[3]));
                o1[0] = fmaf(h10, w20.x, fmaf(h11, w21.x, o1[0]));
                o1[1] = fmaf(h10, w20.y, fmaf(h11, w21.y, o1[1]));
                o1[2] = fmaf(h10, w20.z, fmaf(h11, w21.z, o1[2]));
                o1[3] = fmaf(h10, w20.w, fmaf(h11, w21.w, o1[3]));
            }
        }
    }

    // ---- reduce over the 4 lanes sharing a row, then across warps ----
    #pragma unroll
    for (int i = 0; i < 4; i++)
        #pragma unroll
        for (int o = 0; o < 4; o++) {
            float v = acc_out[i][o];
            v += __shfl_xor_sync(0xffffffffu, v, 1);
            v += __shfl_xor_sync(0xffffffffu, v, 2);
            acc_out[i][o] = v;
        }
    if ((lane & 3) == 0) {
        #pragma unroll
        for (int m = 0; m < 2; m++) {
            #pragma unroll
            for (int rh = 0; rh < 2; rh++) {
                int row = warp_m * 32 + m * 16 + (lane >> 2) + rh * 8;
                #pragma unroll
                for (int o = 0; o < 4; o++)
                    atomicAdd(&red_s[row * 4 + o], acc_out[m * 2 + rh][o]);
            }
        }
    }
    __syncthreads();

    if (tid < BM) {
        float4 v = *(const float4*)(red_s + tid * 4);
        #pragma unroll
        for (int e = 0; e < NEXP; e++) {
            float wpe = wgt_s[tid * NEXP + e];
            v.x = fmaf(wpe, __ldg(&b2[e * 4 + 0]), v.x);
            v.y = fmaf(wpe, __ldg(&b2[e * 4 + 1]), v.y);
            v.z = fmaf(wpe, __ldg(&b2[e * 4 + 2]), v.z);
            v.w = fmaf(wpe, __ldg(&b2[e * 4 + 3]), v.w);
        }
        *(float4*)(out + (size_t)pidx_s[tid] * 4) = v;
    }
}

extern "C" void kernel_launch(void* const* d_in, const int* in_sizes, int n_in,
                              void* d_out, int out_size)
{
    const float* x    = (const float*)d_in[0];
    const float* cent = (const float*)d_in[1];
    const float* W1   = (const float*)d_in[2];
    const float* b1   = (const float*)d_in[3];
    const float* W2   = (const float*)d_in[4];
    const float* b2   = (const float*)d_in[5];
    float* out = (float*)d_out;
    (void)in_sizes; (void)n_in; (void)out_size;

    prep_kernel<<<(NEXP * FRAG_B_U32 + 255) / 256, 256>>>(W1);
    hist_zero_kernel<<<1, 256>>>();
    mask_hist_kernel<<<NPTS / 256, 256>>>(x, cent);
    scan_kernel<<<1, 256>>>();
    scatter_kernel<<<NPTS / 256, 256>>>();

    cudaFuncSetAttribute(meganerf_mma_kernel,
                         cudaFuncAttributeMaxDynamicSharedMemorySize, SMEM_BYTES);
    meganerf_mma_kernel<<<NPTS / BM, NTH, SMEM_BYTES>>>(x, cent, b1, W2, b2, out);
}

// round 17
// speedup vs baseline: 1.9945x; 1.1485x over previous
#include <cuda_runtime.h>
#include <cuda_fp16.h>
#include <cstdint>

// MegaNeRF MoE head via mma.sync (HMMA) + gate-sparse expert skipping.
// Round 16: fp16 2-TERM split (A = Ahi + Alo fp16; B single fp16).
//   - Error: A-split residual ~2^-21; dominant = B fp16 truncation 2^-11
//     -> predicted rel_err ~1e-4 (gate 1e-3). fp32 accumulate.
//   - HMMA per phase -33% (2 terms vs 3); B smem traffic & buffers halve.
//   - Halved buffers enable a 3-STAGE cp.async pipeline (wait_group 2):
//     each copy has two phases of slack -> latency fully hidden.

#define NPTS   131072
#define NEXP   8
#define DIN    90
#define HID    256
#define XCOLS  93
#define BM     128
#define NTH    256
#define NKS    6                          // k-steps of 16 (K=96 padded)
#define NTILES 32
#define MTILES 8
#define FRAG_B_U32 (NTILES * NKS * 64)    // 12288 u32 (single fp16 split)
#define FRAG_A_U32 (MTILES * NKS * 128)   // 6144  u32 per split (hi / lo)
#define QB_U32     (FRAG_B_U32 / 4)       // 3072 u32 per quarter
#define BUF_BYTES  (QB_U32 * 4 + 1280)    // B quarter + b1q(256B) + W2q(1024B)
#define OFF_B1Q    (QB_U32 * 4)           // 12288
#define OFF_W2Q    (OFF_B1Q + 256)        // 12544

__device__ uint32_t g_w1frag[NEXP][FRAG_B_U32];
__device__ int           g_perm[NPTS];
__device__ unsigned      g_hist[256];
__device__ unsigned      g_cursor[256];
__device__ unsigned char g_mask[NPTS];

// ---- smem byte offsets ----
#define SO_WGT  0                                  // 4096
#define SO_RED  4096                               // 2048
#define SO_PIDX 6144                               // 512
#define SO_LIST 6656                               // 64
#define SO_A    6720                               // 49152 (A hi+lo fp16 frags)
#define SO_BUF0 55872                              // 3 x 13568 = 40704
#define SO_X    SO_BUF0                            // x tile aliases buffers
#define SMEM_BYTES (SO_BUF0 + 49152)               // 105024 B (2 CTAs/SM)

// ---- prep: W1 -> fragment-major fp16 (runs once per launch) ----
static __global__ void prep_kernel(const float* __restrict__ W1) {
    int gid = blockIdx.x * blockDim.x + threadIdx.x;
    if (gid >= NEXP * FRAG_B_U32) return;
    int e   = gid / FRAG_B_U32;
    int f   = gid % FRAG_B_U32;
    int nt  = f / (NKS * 64);
    int rem = f % (NKS * 64);
    int ks  = rem >> 6;
    int l2  = rem & 63;
    int lane = l2 >> 1, reg = l2 & 1;
    int n  = nt * 8 + (lane >> 2);
    int k0 = ks * 16 + (lane & 3) * 2 + reg * 8;
    const float* w = W1 + (size_t)e * DIN * HID;
    float v0 = (k0     < DIN) ? __ldg(w + k0 * HID + n)       : 0.0f;
    float v1 = (k0 + 1 < DIN) ? __ldg(w + (k0 + 1) * HID + n) : 0.0f;
    __half h0 = __float2half_rn(v0), h1 = __float2half_rn(v1);
    g_w1frag[e][f] = (uint32_t)__half_as_ushort(h0)
                   | ((uint32_t)__half_as_ushort(h1) << 16);
}

// ---- binning pre-pass ----
static __global__ void hist_zero_kernel() { g_hist[threadIdx.x] = 0u; }

static __global__ void mask_hist_kernel(const float* __restrict__ x,
                                        const float* __restrict__ cent) {
    int i = blockIdx.x * blockDim.x + threadIdx.x;
    const float* xr = x + (size_t)i * XCOLS;
    float px = __ldg(xr + 0), py = __ldg(xr + 1), pz = __ldg(xr + 2);
    float d[NEXP], mind = 3.402823466e38f;
    #pragma unroll
    for (int e = 0; e < NEXP; e++) {
        float dx = px - __ldg(&cent[e * 3 + 0]);
        float dy = py - __ldg(&cent[e * 3 + 1]);
        float dz = pz - __ldg(&cent[e * 3 + 2]);
        float dd = sqrtf(dx * dx + dy * dy + dz * dz);
        d[e] = dd; mind = fminf(mind, dd);
    }
    float thr = 2.0f * mind;
    unsigned m = 0;
    #pragma unroll
    for (int e = 0; e < NEXP; e++)
        if (!(d[e] > thr)) m |= 1u << e;
    g_mask[i] = (unsigned char)m;
    atomicAdd(&g_hist[m], 1u);
}

static __global__ void scan_kernel() {
    __shared__ unsigned s[256];
    int t = threadIdx.x;
    unsigned own = g_hist[t];
    s[t] = own;
    __syncthreads();
    for (int off = 1; off < 256; off <<= 1) {
        unsigned v = (t >= off) ? s[t - off] : 0u;
        __syncthreads();
        s[t] += v;
        __syncthreads();
    }
    g_cursor[t] = s[t] - own;   // exclusive prefix
}

static __global__ void scatter_kernel() {
    int i = blockIdx.x * blockDim.x + threadIdx.x;
    unsigned m = g_mask[i];
    unsigned pos = atomicAdd(&g_cursor[m], 1u);
    g_perm[pos] = i;
}

__device__ __forceinline__ void mma16816(float* d, const uint32_t* a,
                                         const uint32_t* b) {
    asm volatile(
        "mma.sync.aligned.m16n8k16.row.col.f32.f16.f16.f32 "
        "{%0,%1,%2,%3}, {%4,%5,%6,%7}, {%8,%9}, {%0,%1,%2,%3};"
        : "+f"(d[0]), "+f"(d[1]), "+f"(d[2]), "+f"(d[3])
        : "r"(a[0]), "r"(a[1]), "r"(a[2]), "r"(a[3]), "r"(b[0]), "r"(b[1]));
}

__device__ __forceinline__ void cp_async16(uint32_t dst, const void* src) {
    asm volatile("cp.async.cg.shared.global [%0], [%1], 16;"
                 :: "r"(dst), "l"(src) : "memory");
}

// prefetch B (single split) + epilogue params for (expert e, quarter q)
__device__ __forceinline__ void issue_b_copy(int e, int q, uint32_t dst_u32,
                                             int tid,
                                             const float* __restrict__ b1,
                                             const float* __restrict__ W2) {
    const char* src = (const char*)&g_w1frag[e][q * QB_U32];
    #pragma unroll
    for (int i = tid; i < QB_U32 / 4; i += NTH)
        cp_async16(dst_u32 + 16u * i, src + 16 * i);
    if (tid < 16)
        cp_async16(dst_u32 + OFF_B1Q + 16u * tid,
                   (const char*)(b1 + e * HID + q * 64) + 16 * tid);
    else if (tid < 80)
        cp_async16(dst_u32 + OFF_W2Q + 16u * (tid - 16),
                   (const char*)(W2 + ((size_t)e * HID + q * 64) * 4)
                       + 16 * (tid - 16));
    asm volatile("cp.async.commit_group;" ::: "memory");
}

static __global__ void __launch_bounds__(NTH, 2)
meganerf_mma_kernel(const float* __restrict__ x,
                    const float* __restrict__ cent,
                    const float* __restrict__ b1,
                    const float* __restrict__ W2,
                    const float* __restrict__ b2,
                    float* __restrict__ out)
{
    extern __shared__ char smem[];
    float*    wgt_s  = (float*)(smem + SO_WGT);
    float*    red_s  = (float*)(smem + SO_RED);
    int*      pidx_s = (int*)(smem + SO_PIDX);
    unsigned* ls     = (unsigned*)(smem + SO_LIST);
    uint32_t* As     = (uint32_t*)(smem + SO_A);
    float*    xs     = (float*)(smem + SO_X);
    char*     bufc[3] = { smem + SO_BUF0, smem + SO_BUF0 + BUF_BYTES,
                          smem + SO_BUF0 + 2 * BUF_BYTES };
    const uint32_t buf_u32[3] = {
        (uint32_t)__cvta_generic_to_shared(bufc[0]),
        (uint32_t)__cvta_generic_to_shared(bufc[1]),
        (uint32_t)__cvta_generic_to_shared(bufc[2]) };

    const int tid    = threadIdx.x;
    const int lane   = tid & 31;
    const int wid    = tid >> 5;
    const int warp_m = wid & 3;
    const int warp_n = wid >> 2;
    const long n0    = (long)blockIdx.x * BM;

    if (tid < BM) pidx_s[tid] = g_perm[n0 + tid];
    if (tid == 0) ls[0] = 0u;
    __syncthreads();

    // ---- gather permuted x rows into xs [128][96] ----
    for (int i = tid; i < BM * XCOLS; i += NTH) {
        int p = i / XCOLS, c = i - p * XCOLS;
        xs[p * 96 + c] = __ldg(x + (size_t)pidx_s[p] * XCOLS + c);
    }
    for (int i = tid; i < BM * 4; i += NTH) red_s[i] = 0.0f;
    __syncthreads();

    // ---- gating weights + per-CTA active mask ----
    if (tid < BM) {
        float px = xs[tid * 96 + 0], py = xs[tid * 96 + 1], pz = xs[tid * 96 + 2];
        float d[NEXP], mind = 3.402823466e38f;
        #pragma unroll
        for (int e = 0; e < NEXP; e++) {
            float dx = px - __ldg(&cent[e * 3 + 0]);
            float dy = py - __ldg(&cent[e * 3 + 1]);
            float dz = pz - __ldg(&cent[e * 3 + 2]);
            float dd = sqrtf(dx * dx + dy * dy + dz * dz);
            d[e] = dd; mind = fminf(mind, dd);
        }
        float thr = 2.0f * mind, s = 0.0f, inv[NEXP];
        unsigned m = 0;
        #pragma unroll
        for (int e = 0; e < NEXP; e++) {
            float iv = (d[e] > thr) ? 0.0f : 1.0f / (d[e] + 1e-8f);
            if (iv > 0.0f) m |= 1u << e;
            inv[e] = iv; s += iv;
        }
        float rs = 1.0f / s;
        #pragma unroll
        for (int e = 0; e < NEXP; e++) wgt_s[tid * NEXP + e] = inv[e] * rs;
        atomicOr(&ls[0], m);
    }

    // ---- build A fragments (fp16 hi / lo) from xs ----
    for (int f = tid; f < FRAG_A_U32; f += NTH) {
        int mt  = f / (NKS * 128);
        int rem = f % (NKS * 128);
        int ks  = rem >> 7;
        int l2  = rem & 127;
        int lf  = l2 >> 2, rg = l2 & 3;
        int row = mt * 16 + (lf >> 2) + (rg & 1) * 8;
        int k0  = ks * 16 + (lf & 3) * 2 + (rg >> 1) * 8;
        float v0 = (k0     < DIN) ? xs[row * 96 + 3 + k0]     : 0.0f;
        float v1 = (k0 + 1 < DIN) ? xs[row * 96 + 3 + k0 + 1] : 0.0f;
        __half h0 = __float2half_rn(v0), h1 = __float2half_rn(v1);
        __half l0 = __float2half_rn(v0 - __half2float(h0));
        __half l1 = __float2half_rn(v1 - __half2float(h1));
        As[f]              = (uint32_t)__half_as_ushort(h0)
                           | ((uint32_t)__half_as_ushort(h1) << 16);
        As[FRAG_A_U32 + f] = (uint32_t)__half_as_ushort(l0)
                           | ((uint32_t)__half_as_ushort(l1) << 16);
    }
    __syncthreads();   // xs consumed; active mask complete

    if (tid == 0) {
        unsigned m = ls[0], c = 0;
        #pragma unroll
        for (int e = 0; e < NEXP; e++)
            if (m & (1u << e)) ls[2 + c++] = (unsigned)e;
        ls[1] = c;
    }
    __syncthreads();

    const int nact = (int)ls[1];
    const int nph  = nact * 4;

    // 3-stage pipeline priming
    issue_b_copy((int)ls[2], 0, buf_u32[0], tid, b1, W2);
    if (nph > 1)
        issue_b_copy((int)ls[2 + (1 >> 2)], 1 & 3, buf_u32[1], tid, b1, W2);

    float acc_out[4][4];
    #pragma unroll
    for (int i = 0; i < 4; i++)
        #pragma unroll
        for (int o = 0; o < 4; o++) acc_out[i][o] = 0.0f;

    for (int p = 0; p < nph; p++) {
        const int e = (int)ls[2 + (p >> 2)];
        const int slot = p % 3;
        __syncthreads();   // readers of slot (p+2)%3 (phase p-1) done
        if (p + 2 < nph) {
            issue_b_copy((int)ls[2 + ((p + 2) >> 2)], (p + 2) & 3,
                         buf_u32[(p + 2) % 3], tid, b1, W2);
            asm volatile("cp.async.wait_group 2;" ::: "memory");
        } else if (p + 1 < nph) {
            asm volatile("cp.async.wait_group 1;" ::: "memory");
        } else {
            asm volatile("cp.async.wait_group 0;" ::: "memory");
        }
        __syncthreads();   // buffer `slot` ready for all warps

        const uint32_t* Bq  = (const uint32_t*)bufc[slot];
        const float*    b1q = (const float*)(bufc[slot] + OFF_B1Q);
        const float*    w2q = (const float*)(bufc[slot] + OFF_W2Q);

        float wp[2][2];
        #pragma unroll
        for (int m = 0; m < 2; m++) {
            int r0 = warp_m * 32 + m * 16 + (lane >> 2);
            wp[m][0] = wgt_s[r0 * NEXP + e];
            wp[m][1] = wgt_s[(r0 + 8) * NEXP + e];
        }

        float acc[2][4][4];
        #pragma unroll
        for (int m = 0; m < 2; m++)
            #pragma unroll
            for (int n = 0; n < 4; n++)
                #pragma unroll
                for (int r = 0; r < 4; r++) acc[m][n][r] = 0.0f;

        #pragma unroll
        for (int ks = 0; ks < NKS; ks++) {
            uint32_t ah[2][4], al[2][4], bq[4][2];
            #pragma unroll
            for (int m = 0; m < 2; m++) {
                int mt = warp_m * 2 + m;
                *(uint4*)ah[m] = *(const uint4*)(As
                    + (mt * NKS + ks) * 128 + lane * 4);
                *(uint4*)al[m] = *(const uint4*)(As + FRAG_A_U32
                    + (mt * NKS + ks) * 128 + lane * 4);
            }
            #pragma unroll
            for (int n = 0; n < 4; n++) {
                int ln = warp_n * 4 + n;
                *(uint2*)bq[n] = *(const uint2*)(Bq
                    + (ln * NKS + ks) * 64 + lane * 2);
            }
            #pragma unroll
            for (int m = 0; m < 2; m++)
                #pragma unroll
                for (int n = 0; n < 4; n++)
                    mma16816(acc[m][n], ah[m], bq[n]);
            #pragma unroll
            for (int m = 0; m < 2; m++)
                #pragma unroll
                for (int n = 0; n < 4; n++)
                    mma16816(acc[m][n], al[m], bq[n]);
        }

        // ---- epilogue: bias+relu+gate, contract with W2 (staged smem) ----
        #pragma unroll
        for (int n = 0; n < 4; n++) {
            int c = (warp_n * 4 + n) * 8 + (lane & 3) * 2;   // 0..63 in quarter
            float2 b1v = *(const float2*)(b1q + c);
            float4 w20 = *(const float4*)(w2q + c * 4);
            float4 w21 = *(const float4*)(w2q + (c + 1) * 4);
            #pragma unroll
            for (int m = 0; m < 2; m++) {
                float* A = acc[m][n];
                float h00 = fmaxf(A[0] + b1v.x, 0.0f) * wp[m][0];
                float h01 = fmaxf(A[1] + b1v.y, 0.0f) * wp[m][0];
                float h10 = fmaxf(A[2] + b1v.x, 0.0f) * wp[m][1];
                float h11 = fmaxf(A[3] + b1v.y, 0.0f) * wp[m][1];
                float* o0 = acc_out[m * 2];
                float* o1 = acc_out[m * 2 + 1];
                o0[0] = fmaf(h00, w20.x, fmaf(h01, w21.x, o0[0]));
                o0[1] = fmaf(h00, w20.y, fmaf(h01, w21.y, o0[1]));
                o0[2] = fmaf(h00, w20.z, fmaf(h01, w21.z, o0[2]));
                o0[3] = fmaf(h00, w20.w, fmaf(h01, w21.w, o0[3]));
                o1[0] = fmaf(h10, w20.x, fmaf(h11, w21.x, o1[0]));
                o1[1] = fmaf(h10, w20.y, fmaf(h11, w21.y, o1[1]));
                o1[2] = fmaf(h10, w20.z, fmaf(h11, w21.z, o1[2]));
                o1[3] = fmaf(h10, w20.w, fmaf(h11, w21.w, o1[3]));
            }
        }
    }

    // ---- reduce over the 4 lanes sharing a row, then across warps ----
    #pragma unroll
    for (int i = 0; i < 4; i++)
        #pragma unroll
        for (int o = 0; o < 4; o++) {
            float v = acc_out[i][o];
            v += __shfl_xor_sync(0xffffffffu, v, 1);
            v += __shfl_xor_sync(0xffffffffu, v, 2);
            acc_out[i][o] = v;
        }
    if ((lane & 3) == 0) {
        #pragma unroll
        for (int m = 0; m < 2; m++) {
            #pragma unroll
            for (int rh = 0; rh < 2; rh++) {
                int row = warp_m * 32 + m * 16 + (lane >> 2) + rh * 8;
                #pragma unroll
                for (int o = 0; o < 4; o++)
                    atomicAdd(&red_s[row * 4 + o], acc_out[m * 2 + rh][o]);
            }
        }
    }
    __syncthreads();

    if (tid < BM) {
        float4 v = *(const float4*)(red_s + tid * 4);
        #pragma unroll
        for (int e = 0; e < NEXP; e++) {
            float wpe = wgt_s[tid * NEXP + e];
            v.x = fmaf(wpe, __ldg(&b2[e * 4 + 0]), v.x);
            v.y = fmaf(wpe, __ldg(&b2[e * 4 + 1]), v.y);
            v.z = fmaf(wpe, __ldg(&b2[e * 4 + 2]), v.z);
            v.w = fmaf(wpe, __ldg(&b2[e * 4 + 3]), v.w);
        }
        *(float4*)(out + (size_t)pidx_s[tid] * 4) = v;
    }
}

extern "C" void kernel_launch(void* const* d_in, const int* in_sizes, int n_in,
                              void* d_out, int out_size)
{
    const float* x    = (const float*)d_in[0];
    const float* cent = (const float*)d_in[1];
    const float* W1   = (const float*)d_in[2];
    const float* b1   = (const float*)d_in[3];
    const float* W2   = (const float*)d_in[4];
    const float* b2   = (const float*)d_in[5];
    float* out = (float*)d_out;
    (void)in_sizes; (void)n_in; (void)out_size;

    prep_kernel<<<(NEXP * FRAG_B_U32 + 255) / 256, 256>>>(W1);
    hist_zero_kernel<<<1, 256>>>();
    mask_hist_kernel<<<NPTS / 256, 256>>>(x, cent);
    scan_kernel<<<1, 256>>>();
    scatter_kernel<<<NPTS / 256, 256>>>();

    cudaFuncSetAttribute(meganerf_mma_kernel,
                         cudaFuncAttributeMaxDynamicSharedMemorySize, SMEM_BYTES);
    meganerf_mma_kernel<<<NPTS / BM, NTH, SMEM_BYTES>>>(x, cent, b1, W2, b2, out);
}